// round 2
// baseline (speedup 1.0000x reference)
#include <cuda_runtime.h>
#include <math.h>

typedef unsigned long long ull;

#define B_TOT 8192
#define T_TOT 128
#define NNODE 5
#define FML   64
#define F0    256
#define DIN   130          // (FML+1)*2
#define KFEAT 325          // (FML+1)*NODE
#define TILE_B 64
#define NTHR   256
#define KT     16
#define STATE_STRIDE (NNODE*FML)   // 320

__constant__ int c_par[NNODE][2] = {{3,4},{0,4},{0,1},{1,2},{2,3}};

// Scratch (static device globals — no allocations allowed)
__device__ float g_state[2][(size_t)B_TOT*STATE_STRIDE]; // 2 x 10.5 MB ping-pong
__device__ float g_h[(size_t)B_TOT*F0];                  // 8 MB head activations
__device__ float g_psum[(B_TOT/TILE_B)*F0];
__device__ float g_psq [(B_TOT/TILE_B)*F0];
__device__ float g_scale[F0];
__device__ float g_shift[F0];

// ---------- packed f32x2 helpers (sm_100+: fma.rn.f32x2) ----------
__device__ __forceinline__ ull fma2(ull a, ull b, ull c) {
    ull d;
    asm("fma.rn.f32x2 %0, %1, %2, %3;" : "=l"(d) : "l"(a), "l"(b), "l"(c));
    return d;
}
__device__ __forceinline__ ull pack2(float x, float y) {
    ull d;
    asm("mov.b64 %0, {%1, %2};" : "=l"(d) : "f"(x), "f"(y));
    return d;
}
__device__ __forceinline__ float2 unpack2(ull v) {
    float2 r;
    asm("mov.b64 {%0, %1}, %2;" : "=f"(r.x), "=f"(r.y) : "l"(v));
    return r;
}
__device__ __forceinline__ float f4get(const float4& v, int q) {
    switch (q) { case 0: return v.x; case 1: return v.y; case 2: return v.z; default: return v.w; }
}

// ---------- W-tile (KT x 256) load/store: 4 float4 per thread ----------
__device__ __forceinline__ void ldw256(const float* __restrict__ gW, int K, int kbase,
                                       int tid, float4* pre) {
#pragma unroll
    for (int p = 0; p < 4; p++) {
        int q = p*NTHR + tid;
        int row = q >> 6, c4 = q & 63;     // 64 float4 per 256-col row
        float4 v = make_float4(0.f, 0.f, 0.f, 0.f);
        if (kbase + row < K) v = *(const float4*)(gW + (size_t)(kbase+row)*256 + c4*4);
        pre[p] = v;
    }
}
__device__ __forceinline__ void stw256(float* sW, int tid, const float4* pre) {
#pragma unroll
    for (int p = 0; p < 4; p++) {
        int q = p*NTHR + tid;
        int row = q >> 6, c4 = q & 63;
        *(float4*)(sW + row*256 + c4*4) = pre[p];
    }
}

// ---------- GEMM: [64 x K] @ [K x 256] + bias, relu -> sOut ----------
__device__ __forceinline__ void gemm256(const float* __restrict__ sA, int lda,
                                        const float* __restrict__ gW, int K,
                                        const float* __restrict__ gb,
                                        float* __restrict__ sOut, int ldo,
                                        float* sW, int tid)
{
    const int tm = tid >> 5, tn = tid & 31;
    const int m0 = tm * 8, n0 = tn * 8;
    ull acc[8][4];
#pragma unroll
    for (int i = 0; i < 8; i++)
#pragma unroll
        for (int j = 0; j < 4; j++) acc[i][j] = 0ull;

    const int nt = (K + KT - 1) / KT;
    float4 pre[4];
    ldw256(gW, K, 0, tid, pre);
    stw256(sW, tid, pre);
    __syncthreads();
    int buf = 0;
    for (int kt = 0; kt < nt; kt++) {
        if (kt + 1 < nt) ldw256(gW, K, (kt+1)*KT, tid, pre);
        const float* Wb = sW + buf * (KT*256);
        const int kbase = kt * KT;
        int kcnt = K - kbase; if (kcnt > KT) kcnt = KT;
        if (kcnt == KT) {
#pragma unroll
            for (int kk = 0; kk < KT; kk += 4) {
                float4 a4[8];
#pragma unroll
                for (int i = 0; i < 8; i++)
                    a4[i] = *(const float4*)(sA + (m0+i)*lda + kbase + kk);
#pragma unroll
                for (int q = 0; q < 4; q++) {
                    const ull* bp = (const ull*)(Wb + (kk+q)*256 + n0);
                    ull w0 = bp[0], w1 = bp[1], w2 = bp[2], w3 = bp[3];
#pragma unroll
                    for (int i = 0; i < 8; i++) {
                        float av = f4get(a4[i], q);
                        ull aa = pack2(av, av);
                        acc[i][0] = fma2(aa, w0, acc[i][0]);
                        acc[i][1] = fma2(aa, w1, acc[i][1]);
                        acc[i][2] = fma2(aa, w2, acc[i][2]);
                        acc[i][3] = fma2(aa, w3, acc[i][3]);
                    }
                }
            }
        } else {
            for (int kk = 0; kk < kcnt; kk++) {
                const ull* bp = (const ull*)(Wb + kk*256 + n0);
                ull w0 = bp[0], w1 = bp[1], w2 = bp[2], w3 = bp[3];
#pragma unroll
                for (int i = 0; i < 8; i++) {
                    float av = sA[(m0+i)*lda + kbase + kk];
                    ull aa = pack2(av, av);
                    acc[i][0] = fma2(aa, w0, acc[i][0]);
                    acc[i][1] = fma2(aa, w1, acc[i][1]);
                    acc[i][2] = fma2(aa, w2, acc[i][2]);
                    acc[i][3] = fma2(aa, w3, acc[i][3]);
                }
            }
        }
        __syncthreads();
        if (kt + 1 < nt) {
            stw256(sW + (buf^1) * (KT*256), tid, pre);
            __syncthreads();
        }
        buf ^= 1;
    }
    float bb[8];
#pragma unroll
    for (int j = 0; j < 8; j++) bb[j] = gb[n0 + j];
#pragma unroll
    for (int i = 0; i < 8; i++) {
#pragma unroll
        for (int j = 0; j < 4; j++) {
            float2 v = unpack2(acc[i][j]);
            v.x = fmaxf(v.x + bb[2*j],   0.f);
            v.y = fmaxf(v.y + bb[2*j+1], 0.f);
            *(float2*)(sOut + (m0+i)*ldo + n0 + 2*j) = v;
        }
    }
}

// ---------- GEMM: [64 x 256] @ [256 x 64] + bias, tanh -> global state ----------
__device__ __forceinline__ void gemm64_tanh(const float* __restrict__ sA, int lda,
                                            const float* __restrict__ gW,
                                            const float* __restrict__ gb,
                                            float* __restrict__ gOut,  // + b0*320 + nd*64
                                            float* sW, int tid)
{
    const int K = F0;                      // 256 exact
    const int tm = tid >> 5, tn = tid & 31;
    const int m0 = tm * 8, n0 = tn * 2;
    ull acc[8];
#pragma unroll
    for (int i = 0; i < 8; i++) acc[i] = 0ull;

    const int nt = K / KT;                 // 16
    const int lrow = tid >> 4, lc4 = tid & 15;   // 16 float4 per 64-col row
    float4 pre = *(const float4*)(gW + (size_t)lrow*64 + lc4*4);
    *(float4*)(sW + lrow*64 + lc4*4) = pre;
    __syncthreads();
    int buf = 0;
    for (int kt = 0; kt < nt; kt++) {
        if (kt + 1 < nt)
            pre = *(const float4*)(gW + (size_t)((kt+1)*KT + lrow)*64 + lc4*4);
        const float* Wb = sW + buf * (KT*64);
        const int kbase = kt * KT;
#pragma unroll
        for (int kk = 0; kk < KT; kk += 4) {
            float4 a4[8];
#pragma unroll
            for (int i = 0; i < 8; i++)
                a4[i] = *(const float4*)(sA + (m0+i)*lda + kbase + kk);
#pragma unroll
            for (int q = 0; q < 4; q++) {
                ull w = *(const ull*)(Wb + (kk+q)*64 + n0);
#pragma unroll
                for (int i = 0; i < 8; i++) {
                    float av = f4get(a4[i], q);
                    acc[i] = fma2(pack2(av, av), w, acc[i]);
                }
            }
        }
        __syncthreads();
        if (kt + 1 < nt) {
            *(float4*)(sW + (buf^1)*(KT*64) + lrow*64 + lc4*4) = pre;
            __syncthreads();
        }
        buf ^= 1;
    }
    const float bx = gb[n0], by = gb[n0+1];
#pragma unroll
    for (int i = 0; i < 8; i++) {
        float2 v = unpack2(acc[i]);
        float2 o;
        o.x = tanhf(v.x + bx);
        o.y = tanhf(v.y + by);
        *(float2*)(gOut + (size_t)(m0+i)*STATE_STRIDE + n0) = o;
    }
}

// ---------- one recurrent timestep ----------
__global__ __launch_bounds__(NTHR) void step_kernel(
    const float* __restrict__ x,
    const float* __restrict__ W1, const float* __restrict__ b1,
    const float* __restrict__ W2, const float* __restrict__ b2,
    const float* __restrict__ W3, const float* __restrict__ b3,
    int t)
{
    extern __shared__ float smem[];
    float* sA  = smem;                       // 64*132
    float* sH1 = sA  + TILE_B*132;           // 64*260
    float* sH2 = sH1 + TILE_B*260;           // 64*260
    float* sW  = sH2 + TILE_B*260;           // 2*16*256

    const int tid = threadIdx.x;
    const int nd  = blockIdx.y;
    const int b0  = blockIdx.x * TILE_B;
    const int rd  = t & 1, wr = rd ^ 1;
    const int p0  = c_par[nd][0], p1 = c_par[nd][1];
    const float* stp = g_state[rd];

    // assemble inp = [x_p0, x_p1, state_p0(64), state_p1(64)]
    for (int i = tid; i < TILE_B * 2*FML; i += NTHR) {
        int m = i >> 7, c = i & 127;
        int p = (c < FML) ? p0 : p1;
        sA[m*132 + 2 + c] = stp[(size_t)(b0+m)*STATE_STRIDE + p*FML + (c & (FML-1))];
    }
    if (tid < TILE_B * 2) {
        int m = tid >> 1, w = tid & 1;
        int p = w ? p1 : p0;
        sA[m*132 + w] = x[(size_t)(b0+m)*(NNODE*T_TOT) + p*T_TOT + t];
    }
    __syncthreads();

    gemm256(sA,  132, W1 + nd*(DIN*F0), DIN, b1 + nd*F0, sH1, 260, sW, tid);
    __syncthreads();
    gemm256(sH1, 260, W2 + nd*(F0*F0),  F0,  b2 + nd*F0, sH2, 260, sW, tid);
    __syncthreads();
    gemm64_tanh(sH2, 260, W3 + nd*(F0*FML), b3 + nd*FML,
                g_state[wr] + (size_t)b0*STATE_STRIDE + nd*FML, sW, tid);
}

// ---------- head GEMM (K=325) + deterministic BN partials ----------
__global__ __launch_bounds__(NTHR) void final1_kernel(
    const float* __restrict__ x,
    const float* __restrict__ Wo1, const float* __restrict__ bo1)
{
    extern __shared__ float smem[];
    float* sF = smem;                        // 64*328
    float* sH = sF + TILE_B*328;             // 64*260
    float* sW = sH + TILE_B*260;             // 2*16*256
    const int tid = threadIdx.x;
    const int b0  = blockIdx.x * TILE_B;
    const float* st = g_state[0];            // after t=127, state lives in buffer 0

    for (int i = tid; i < TILE_B*STATE_STRIDE; i += NTHR) {
        int m = i / STATE_STRIDE, c = i % STATE_STRIDE;
        sF[m*328 + NNODE + c] = st[(size_t)(b0+m)*STATE_STRIDE + c];
    }
    // FIX (R1): TILE_B*NNODE = 320 > NTHR = 256, so this must be a strided
    // loop — the old `if (tid < TILE_B*NNODE)` left rows 52..63 of every tile
    // with uninitialized x-features, which corrupted the BN stats globally.
    for (int i = tid; i < TILE_B*NNODE; i += NTHR) {
        int m = i / NNODE, nn = i % NNODE;
        sF[m*328 + nn] = x[(size_t)(b0+m)*(NNODE*T_TOT) + nn*T_TOT + (T_TOT-1)];
    }
    __syncthreads();

    gemm256(sF, 328, Wo1, KFEAT, bo1, sH, 260, sW, tid);
    __syncthreads();

    for (int i = tid; i < TILE_B*F0; i += NTHR) {
        int m = i >> 8, c = i & 255;
        g_h[(size_t)(b0+m)*F0 + c] = sH[m*260 + c];
    }
    float s = 0.f, q = 0.f;
    for (int m = 0; m < TILE_B; m++) {
        float v = sH[m*260 + tid];
        s += v; q += v*v;
    }
    g_psum[blockIdx.x*F0 + tid] = s;
    g_psq [blockIdx.x*F0 + tid] = q;
}

// ---------- fold BN stats into scale/shift (deterministic) ----------
__global__ void bn_kernel(const float* __restrict__ gamma, const float* __restrict__ beta) {
    int c = threadIdx.x;
    float s = 0.f, q = 0.f;
    for (int b = 0; b < (B_TOT/TILE_B); b++) { s += g_psum[b*F0 + c]; q += g_psq[b*F0 + c]; }
    float mu  = s * (1.f / B_TOT);
    float var = q * (1.f / B_TOT) - mu * mu;
    float rstd = rsqrtf(var + 1e-5f);
    float sc = gamma[c] * rstd;
    g_scale[c] = sc;
    g_shift[c] = beta[c] - mu * sc;
}

// ---------- normalize + 256x7 GEMM + softmax ----------
__global__ __launch_bounds__(NTHR) void final2_kernel(
    const float* __restrict__ Wo2, const float* __restrict__ bo2,
    float* __restrict__ out)
{
    __shared__ float sw2[F0*7];
    __shared__ float sb2[7];
    __shared__ float ssc[F0], ssh[F0];
    const int tid = threadIdx.x;
    for (int i = tid; i < F0*7; i += NTHR) sw2[i] = Wo2[i];
    if (tid < 7) sb2[tid] = bo2[tid];
    ssc[tid] = g_scale[tid];
    ssh[tid] = g_shift[tid];
    __syncthreads();

    const int warp = tid >> 5, lane = tid & 31;
    for (int r = 0; r < 16; r++) {                 // 64 blocks * 8 warps * 16 rows = 8192
        int b = blockIdx.x*128 + warp*16 + r;
        float a0=0,a1=0,a2=0,a3=0,a4=0,a5=0,a6=0;
        const float* hp = g_h + (size_t)b*F0;
#pragma unroll
        for (int kk = 0; kk < 8; kk++) {
            int k = kk*32 + lane;
            float hv = hp[k]*ssc[k] + ssh[k];
            const float* wr = sw2 + k*7;
            a0 += hv*wr[0]; a1 += hv*wr[1]; a2 += hv*wr[2]; a3 += hv*wr[3];
            a4 += hv*wr[4]; a5 += hv*wr[5]; a6 += hv*wr[6];
        }
#pragma unroll
        for (int off = 16; off; off >>= 1) {
            a0 += __shfl_down_sync(0xffffffffu, a0, off);
            a1 += __shfl_down_sync(0xffffffffu, a1, off);
            a2 += __shfl_down_sync(0xffffffffu, a2, off);
            a3 += __shfl_down_sync(0xffffffffu, a3, off);
            a4 += __shfl_down_sync(0xffffffffu, a4, off);
            a5 += __shfl_down_sync(0xffffffffu, a5, off);
            a6 += __shfl_down_sync(0xffffffffu, a6, off);
        }
        if (lane == 0) {
            float l[7] = { a0+sb2[0], a1+sb2[1], a2+sb2[2], a3+sb2[3],
                           a4+sb2[4], a5+sb2[5], a6+sb2[6] };
            float mx = l[0];
#pragma unroll
            for (int j = 1; j < 7; j++) mx = fmaxf(mx, l[j]);
            float e[7], se = 0.f;
#pragma unroll
            for (int j = 0; j < 7; j++) { e[j] = expf(l[j] - mx); se += e[j]; }
            float inv = 1.f / se;
#pragma unroll
            for (int j = 0; j < 7; j++) out[(size_t)b*7 + j] = e[j]*inv;
        }
    }
}

__global__ void zero_state_kernel() {
    size_t n = (size_t)B_TOT*STATE_STRIDE;
    for (size_t i = blockIdx.x*(size_t)blockDim.x + threadIdx.x; i < n;
         i += (size_t)gridDim.x*blockDim.x)
        g_state[0][i] = 0.f;
}

extern "C" void kernel_launch(void* const* d_in, const int* in_sizes, int n_in,
                              void* d_out, int out_size)
{
    (void)in_sizes; (void)n_in; (void)out_size;
    const float* x     = (const float*)d_in[0];
    const float* W1    = (const float*)d_in[1];
    const float* b1    = (const float*)d_in[2];
    const float* W2    = (const float*)d_in[3];
    const float* b2    = (const float*)d_in[4];
    const float* W3    = (const float*)d_in[5];
    const float* b3    = (const float*)d_in[6];
    const float* Wo1   = (const float*)d_in[7];
    const float* bo1   = (const float*)d_in[8];
    const float* gamma = (const float*)d_in[9];
    const float* beta  = (const float*)d_in[10];
    const float* Wo2   = (const float*)d_in[11];
    const float* bo2   = (const float*)d_in[12];
    float* out = (float*)d_out;

    const int STEP_SMEM = (TILE_B*132 + 2*TILE_B*260 + 2*KT*256) * (int)sizeof(float); // 199,680 B
    const int F1_SMEM   = (TILE_B*328 + TILE_B*260 + 2*KT*256) * (int)sizeof(float);   // 183,296 B
    cudaFuncSetAttribute(step_kernel,  cudaFuncAttributeMaxDynamicSharedMemorySize, STEP_SMEM);
    cudaFuncSetAttribute(final1_kernel, cudaFuncAttributeMaxDynamicSharedMemorySize, F1_SMEM);

    zero_state_kernel<<<512, 256>>>();

    dim3 sgrid(B_TOT/TILE_B, NNODE);
    for (int t = 0; t < T_TOT; t++)
        step_kernel<<<sgrid, NTHR, STEP_SMEM>>>(x, W1, b1, W2, b2, W3, b3, t);

    final1_kernel<<<B_TOT/TILE_B, NTHR, F1_SMEM>>>(x, Wo1, bo1);
    bn_kernel<<<1, F0>>>(gamma, beta);
    final2_kernel<<<64, NTHR>>>(Wo2, bo2, out);
}

// round 3
// speedup vs baseline: 1.1326x; 1.1326x over previous
#include <cuda_runtime.h>
#include <math.h>

typedef unsigned long long ull;

#define B_TOT 8192
#define T_TOT 128
#define NNODE 5
#define FML   64
#define F0    256
#define DIN   130          // (FML+1)*2
#define KFEAT 325          // (FML+1)*NODE
#define TILE_B 64
#define NTHR   256
#define KT     16
#define STATE_STRIDE (NNODE*FML)   // 320
#define LDB    260         // BUF leading dim (>= 256 and >= 144)
#define LDF    336         // final feature leading dim (>= 325, mult of 16)

__constant__ int c_par[NNODE][2] = {{3,4},{0,4},{0,1},{1,2},{2,3}};

// Scratch (static device globals — no allocations allowed)
__device__ float g_state[2][(size_t)B_TOT*STATE_STRIDE]; // 2 x 10.5 MB ping-pong
__device__ float g_h[(size_t)B_TOT*F0];                  // 8 MB head activations
__device__ float g_psum[(B_TOT/TILE_B)*F0];
__device__ float g_psq [(B_TOT/TILE_B)*F0];
__device__ float g_scale[F0];
__device__ float g_shift[F0];

// ---------- packed f32x2 helpers (sm_100+: fma.rn.f32x2) ----------
__device__ __forceinline__ ull fma2(ull a, ull b, ull c) {
    ull d;
    asm("fma.rn.f32x2 %0, %1, %2, %3;" : "=l"(d) : "l"(a), "l"(b), "l"(c));
    return d;
}
__device__ __forceinline__ ull pack2(float x, float y) {
    ull d;
    asm("mov.b64 %0, {%1, %2};" : "=l"(d) : "f"(x), "f"(y));
    return d;
}
__device__ __forceinline__ float2 unpack2(ull v) {
    float2 r;
    asm("mov.b64 {%0, %1}, %2;" : "=f"(r.x), "=f"(r.y) : "l"(v));
    return r;
}

// ---------- W-tile (KT x 256) load/store: 4 float4 per thread ----------
__device__ __forceinline__ void ldw256(const float* __restrict__ gW, int K, int kbase,
                                       int tid, float4* pre) {
#pragma unroll
    for (int p = 0; p < 4; p++) {
        int q = p*NTHR + tid;
        int row = q >> 6, c4 = q & 63;     // 64 float4 per 256-col row
        float4 v = make_float4(0.f, 0.f, 0.f, 0.f);
        if (kbase + row < K) v = *(const float4*)(gW + (size_t)(kbase+row)*256 + c4*4);
        pre[p] = v;
    }
}
__device__ __forceinline__ void stw256(float* sW, int tid, const float4* pre) {
#pragma unroll
    for (int p = 0; p < 4; p++) {
        int q = p*NTHR + tid;
        int row = q >> 6, c4 = q & 63;
        *(float4*)(sW + row*256 + c4*4) = pre[p];
    }
}

// ---------- GEMM: [64 x K] @ [K x 256] + bias, relu -> sOut (may alias sA) ----
// Thread (tm=tid>>5, tn=tid&31): rows m0..m0+7, cols tn*2 + 64*j (j=0..3).
// B loads: LDS.64 at 8B lane stride -> conflict-free. A loads: warp-uniform
// broadcast. One __syncthreads per k-tile (store into other buffer pre-sync).
// NOTE: caller must ensure sA cols [K, KT*ceil(K/KT)) are zeroed.
__device__ __forceinline__ void gemm256(const float* __restrict__ sA, int lda,
                                        const float* __restrict__ gW, int K,
                                        const float* __restrict__ gb,
                                        float* __restrict__ sOut, int ldo,
                                        float* sW, int tid)
{
    const int tm = tid >> 5, tn = tid & 31;
    const int m0 = tm * 8, n0 = tn * 2;
    ull acc[8][4];
#pragma unroll
    for (int i = 0; i < 8; i++)
#pragma unroll
        for (int j = 0; j < 4; j++) acc[i][j] = 0ull;

    const int nt = (K + KT - 1) / KT;
    float4 pre[4];
    ldw256(gW, K, 0, tid, pre);
    stw256(sW, tid, pre);
    __syncthreads();
    for (int kt = 0; kt < nt; kt++) {
        if (kt + 1 < nt) ldw256(gW, K, (kt+1)*KT, tid, pre);
        const float* Wb = sW + (kt & 1) * (KT*256);
        const float* Arow = sA + m0*lda + kt*KT;
#pragma unroll
        for (int kk = 0; kk < KT; kk++) {
            const ull* bp = (const ull*)(Wb + kk*256 + n0);
            ull w0 = bp[0], w1 = bp[32], w2 = bp[64], w3 = bp[96];
#pragma unroll
            for (int i = 0; i < 8; i++) {
                float a = Arow[i*lda + kk];
                ull aa = pack2(a, a);
                acc[i][0] = fma2(aa, w0, acc[i][0]);
                acc[i][1] = fma2(aa, w1, acc[i][1]);
                acc[i][2] = fma2(aa, w2, acc[i][2]);
                acc[i][3] = fma2(aa, w3, acc[i][3]);
            }
        }
        if (kt + 1 < nt) stw256(sW + ((kt+1) & 1)*(KT*256), tid, pre);
        __syncthreads();   // also guards overwrite of sA by the epilogue below
    }
    float2 bb[4];
#pragma unroll
    for (int j = 0; j < 4; j++) bb[j] = *(const float2*)(gb + n0 + 64*j);
#pragma unroll
    for (int i = 0; i < 8; i++) {
#pragma unroll
        for (int j = 0; j < 4; j++) {
            float2 v = unpack2(acc[i][j]);
            v.x = fmaxf(v.x + bb[j].x, 0.f);
            v.y = fmaxf(v.y + bb[j].y, 0.f);
            *(float2*)(sOut + (m0+i)*ldo + n0 + 64*j) = v;   // 8B lane stride: conflict-free
        }
    }
}

// ---------- GEMM: [64 x 256] @ [256 x 64] + bias, tanh -> global state ----------
__device__ __forceinline__ void gemm64_tanh(const float* __restrict__ sA, int lda,
                                            const float* __restrict__ gW,
                                            const float* __restrict__ gb,
                                            float* __restrict__ gOut,  // + b0*320 + nd*64
                                            float* sW, int tid)
{
    const int tm = tid >> 5, tn = tid & 31;
    const int m0 = tm * 8, n0 = tn * 2;
    ull acc[8];
#pragma unroll
    for (int i = 0; i < 8; i++) acc[i] = 0ull;

    const int nt = F0 / KT;                      // 16
    const int lrow = tid >> 4, lc4 = tid & 15;   // 16 float4 per 64-col row
    float4 pre = *(const float4*)(gW + (size_t)lrow*64 + lc4*4);
    *(float4*)(sW + lrow*64 + lc4*4) = pre;
    __syncthreads();
    for (int kt = 0; kt < nt; kt++) {
        if (kt + 1 < nt)
            pre = *(const float4*)(gW + (size_t)((kt+1)*KT + lrow)*64 + lc4*4);
        const float* Wb = sW + (kt & 1) * (KT*64);
        const float* Arow = sA + m0*lda + kt*KT;
#pragma unroll
        for (int kk = 0; kk < KT; kk++) {
            ull w = *(const ull*)(Wb + kk*64 + n0);
#pragma unroll
            for (int i = 0; i < 8; i++) {
                float a = Arow[i*lda + kk];
                acc[i] = fma2(pack2(a, a), w, acc[i]);
            }
        }
        if (kt + 1 < nt)
            *(float4*)(sW + ((kt+1) & 1)*(KT*64) + lrow*64 + lc4*4) = pre;
        __syncthreads();
    }
    const float2 bb = *(const float2*)(gb + n0);
#pragma unroll
    for (int i = 0; i < 8; i++) {
        float2 v = unpack2(acc[i]);
        float2 o;
        o.x = tanhf(v.x + bb.x);
        o.y = tanhf(v.y + bb.y);
        *(float2*)(gOut + (size_t)(m0+i)*STATE_STRIDE + n0) = o;
    }
}

// ---------- one recurrent timestep ----------
__global__ __launch_bounds__(NTHR, 2) void step_kernel(
    const float* __restrict__ x,
    const float* __restrict__ W1, const float* __restrict__ b1,
    const float* __restrict__ W2, const float* __restrict__ b2,
    const float* __restrict__ W3, const float* __restrict__ b3,
    int t)
{
    extern __shared__ float smem[];
    float* BUF = smem;                       // 64*260 (reused A/H1/H2)
    float* sW  = BUF + TILE_B*LDB;           // 2*16*256

    const int tid = threadIdx.x;
    const int nd  = blockIdx.y;
    const int b0  = blockIdx.x * TILE_B;
    const int rd  = t & 1, wr = rd ^ 1;
    const int p0  = c_par[nd][0], p1 = c_par[nd][1];
    const float* stp = g_state[rd];

    // assemble inp = [x_p0, x_p1, state_p0(64), state_p1(64)], zero-pad to col 144
    for (int i = tid; i < TILE_B * 2*FML; i += NTHR) {
        int m = i >> 7, c = i & 127;
        int p = (c < FML) ? p0 : p1;
        BUF[m*LDB + 2 + c] = stp[(size_t)(b0+m)*STATE_STRIDE + p*FML + (c & (FML-1))];
    }
    if (tid < TILE_B * 2) {
        int m = tid >> 1, w = tid & 1;
        int p = w ? p1 : p0;
        BUF[m*LDB + w] = x[(size_t)(b0+m)*(NNODE*T_TOT) + p*T_TOT + t];
    }
    for (int i = tid; i < TILE_B * 14; i += NTHR) {    // zero cols 130..143
        int m = i / 14, c = 130 + i % 14;
        BUF[m*LDB + c] = 0.f;
    }
    __syncthreads();

    gemm256(BUF, LDB, W1 + nd*(DIN*F0), DIN, b1 + nd*F0, BUF, LDB, sW, tid);
    __syncthreads();
    gemm256(BUF, LDB, W2 + nd*(F0*F0),  F0,  b2 + nd*F0, BUF, LDB, sW, tid);
    __syncthreads();
    gemm64_tanh(BUF, LDB, W3 + nd*(F0*FML), b3 + nd*FML,
                g_state[wr] + (size_t)b0*STATE_STRIDE + nd*FML, sW, tid);
}

// ---------- head GEMM (K=325) + deterministic BN partials ----------
__global__ __launch_bounds__(NTHR) void final1_kernel(
    const float* __restrict__ x,
    const float* __restrict__ Wo1, const float* __restrict__ bo1)
{
    extern __shared__ float smem[];
    float* sF = smem;                        // 64*336 (features, then H output)
    float* sW = sF + TILE_B*LDF;             // 2*16*256
    const int tid = threadIdx.x;
    const int b0  = blockIdx.x * TILE_B;
    const float* st = g_state[0];            // after t=127, state lives in buffer 0

    for (int i = tid; i < TILE_B*STATE_STRIDE; i += NTHR) {
        int m = i / STATE_STRIDE, c = i % STATE_STRIDE;
        sF[m*LDF + NNODE + c] = st[(size_t)(b0+m)*STATE_STRIDE + c];
    }
    for (int i = tid; i < TILE_B*NNODE; i += NTHR) {
        int m = i / NNODE, nn = i % NNODE;
        sF[m*LDF + nn] = x[(size_t)(b0+m)*(NNODE*T_TOT) + nn*T_TOT + (T_TOT-1)];
    }
    for (int i = tid; i < TILE_B*(LDF-KFEAT); i += NTHR) {   // zero cols 325..335
        int m = i / (LDF-KFEAT), c = KFEAT + i % (LDF-KFEAT);
        sF[m*LDF + c] = 0.f;
    }
    __syncthreads();

    gemm256(sF, LDF, Wo1, KFEAT, bo1, sF, LDF, sW, tid);
    __syncthreads();

    for (int i = tid; i < TILE_B*F0; i += NTHR) {
        int m = i >> 8, c = i & 255;
        g_h[(size_t)(b0+m)*F0 + c] = sF[m*LDF + c];
    }
    float s = 0.f, q = 0.f;
    for (int m = 0; m < TILE_B; m++) {
        float v = sF[m*LDF + tid];
        s += v; q += v*v;
    }
    g_psum[blockIdx.x*F0 + tid] = s;
    g_psq [blockIdx.x*F0 + tid] = q;
}

// ---------- fold BN stats into scale/shift (deterministic) ----------
__global__ void bn_kernel(const float* __restrict__ gamma, const float* __restrict__ beta) {
    int c = threadIdx.x;
    float s = 0.f, q = 0.f;
    for (int b = 0; b < (B_TOT/TILE_B); b++) { s += g_psum[b*F0 + c]; q += g_psq[b*F0 + c]; }
    float mu  = s * (1.f / B_TOT);
    float var = q * (1.f / B_TOT) - mu * mu;
    float rstd = rsqrtf(var + 1e-5f);
    float sc = gamma[c] * rstd;
    g_scale[c] = sc;
    g_shift[c] = beta[c] - mu * sc;
}

// ---------- normalize + 256x7 GEMM + softmax ----------
__global__ __launch_bounds__(NTHR) void final2_kernel(
    const float* __restrict__ Wo2, const float* __restrict__ bo2,
    float* __restrict__ out)
{
    __shared__ float sw2[F0*7];
    __shared__ float sb2[7];
    __shared__ float ssc[F0], ssh[F0];
    const int tid = threadIdx.x;
    for (int i = tid; i < F0*7; i += NTHR) sw2[i] = Wo2[i];
    if (tid < 7) sb2[tid] = bo2[tid];
    ssc[tid] = g_scale[tid];
    ssh[tid] = g_shift[tid];
    __syncthreads();

    const int warp = tid >> 5, lane = tid & 31;
    for (int r = 0; r < 16; r++) {                 // 64 blocks * 8 warps * 16 rows = 8192
        int b = blockIdx.x*128 + warp*16 + r;
        float a0=0,a1=0,a2=0,a3=0,a4=0,a5=0,a6=0;
        const float* hp = g_h + (size_t)b*F0;
#pragma unroll
        for (int kk = 0; kk < 8; kk++) {
            int k = kk*32 + lane;
            float hv = hp[k]*ssc[k] + ssh[k];
            const float* wr = sw2 + k*7;
            a0 += hv*wr[0]; a1 += hv*wr[1]; a2 += hv*wr[2]; a3 += hv*wr[3];
            a4 += hv*wr[4]; a5 += hv*wr[5]; a6 += hv*wr[6];
        }
#pragma unroll
        for (int off = 16; off; off >>= 1) {
            a0 += __shfl_down_sync(0xffffffffu, a0, off);
            a1 += __shfl_down_sync(0xffffffffu, a1, off);
            a2 += __shfl_down_sync(0xffffffffu, a2, off);
            a3 += __shfl_down_sync(0xffffffffu, a3, off);
            a4 += __shfl_down_sync(0xffffffffu, a4, off);
            a5 += __shfl_down_sync(0xffffffffu, a5, off);
            a6 += __shfl_down_sync(0xffffffffu, a6, off);
        }
        if (lane == 0) {
            float l[7] = { a0+sb2[0], a1+sb2[1], a2+sb2[2], a3+sb2[3],
                           a4+sb2[4], a5+sb2[5], a6+sb2[6] };
            float mx = l[0];
#pragma unroll
            for (int j = 1; j < 7; j++) mx = fmaxf(mx, l[j]);
            float e[7], se = 0.f;
#pragma unroll
            for (int j = 0; j < 7; j++) { e[j] = expf(l[j] - mx); se += e[j]; }
            float inv = 1.f / se;
#pragma unroll
            for (int j = 0; j < 7; j++) out[(size_t)b*7 + j] = e[j]*inv;
        }
    }
}

__global__ void zero_state_kernel() {
    size_t n = (size_t)B_TOT*STATE_STRIDE;
    for (size_t i = blockIdx.x*(size_t)blockDim.x + threadIdx.x; i < n;
         i += (size_t)gridDim.x*blockDim.x)
        g_state[0][i] = 0.f;
}

extern "C" void kernel_launch(void* const* d_in, const int* in_sizes, int n_in,
                              void* d_out, int out_size)
{
    (void)in_sizes; (void)n_in; (void)out_size;
    const float* x     = (const float*)d_in[0];
    const float* W1    = (const float*)d_in[1];
    const float* b1    = (const float*)d_in[2];
    const float* W2    = (const float*)d_in[3];
    const float* b2    = (const float*)d_in[4];
    const float* W3    = (const float*)d_in[5];
    const float* b3    = (const float*)d_in[6];
    const float* Wo1   = (const float*)d_in[7];
    const float* bo1   = (const float*)d_in[8];
    const float* gamma = (const float*)d_in[9];
    const float* beta  = (const float*)d_in[10];
    const float* Wo2   = (const float*)d_in[11];
    const float* bo2   = (const float*)d_in[12];
    float* out = (float*)d_out;

    const int STEP_SMEM = (TILE_B*LDB + 2*KT*256) * (int)sizeof(float);  // 99,328 B
    const int F1_SMEM   = (TILE_B*LDF + 2*KT*256) * (int)sizeof(float);  // 118,784 B
    cudaFuncSetAttribute(step_kernel,   cudaFuncAttributeMaxDynamicSharedMemorySize, STEP_SMEM);
    cudaFuncSetAttribute(final1_kernel, cudaFuncAttributeMaxDynamicSharedMemorySize, F1_SMEM);

    zero_state_kernel<<<512, 256>>>();

    dim3 sgrid(B_TOT/TILE_B, NNODE);
    for (int t = 0; t < T_TOT; t++)
        step_kernel<<<sgrid, NTHR, STEP_SMEM>>>(x, W1, b1, W2, b2, W3, b3, t);

    final1_kernel<<<B_TOT/TILE_B, NTHR, F1_SMEM>>>(x, Wo1, bo1);
    bn_kernel<<<1, F0>>>(gamma, beta);
    final2_kernel<<<64, NTHR>>>(Wo2, bo2, out);
}

// round 4
// speedup vs baseline: 1.1332x; 1.0005x over previous
#include <cuda_runtime.h>
#include <math.h>

typedef unsigned long long ull;

#define B_TOT 8192
#define T_TOT 128
#define NNODE 5
#define FML   64
#define F0    256
#define DIN   130          // (FML+1)*2
#define KFEAT 325          // (FML+1)*NODE
#define TILE_B 64
#define NTHR   256
#define KT     16
#define STATE_STRIDE (NNODE*FML)   // 320
#define LDB    260         // BUF leading dim (>= 256 and >= 144)
#define LDF    336         // final feature leading dim (>= 325, mult of 16)

__constant__ int c_par[NNODE][2] = {{3,4},{0,4},{0,1},{1,2},{2,3}};

// Scratch (static device globals — no allocations allowed)
__device__ float g_state[2][(size_t)B_TOT*STATE_STRIDE]; // 2 x 10.5 MB ping-pong
__device__ float g_h[(size_t)B_TOT*F0];                  // 8 MB head activations
__device__ float g_psum[(B_TOT/TILE_B)*F0];
__device__ float g_psq [(B_TOT/TILE_B)*F0];
__device__ float g_scale[F0];
__device__ float g_shift[F0];

// ---------- packed f32x2 helpers (sm_100+: fma.rn.f32x2) ----------
__device__ __forceinline__ ull fma2(ull a, ull b, ull c) {
    ull d;
    asm("fma.rn.f32x2 %0, %1, %2, %3;" : "=l"(d) : "l"(a), "l"(b), "l"(c));
    return d;
}
__device__ __forceinline__ ull pack2(float x, float y) {
    ull d;
    asm("mov.b64 %0, {%1, %2};" : "=l"(d) : "f"(x), "f"(y));
    return d;
}
__device__ __forceinline__ float2 unpack2(ull v) {
    float2 r;
    asm("mov.b64 {%0, %1}, %2;" : "=f"(r.x), "=f"(r.y) : "l"(v));
    return r;
}

// ---------- W-tile (KT x 256) load/store: 4 float4 per thread ----------
__device__ __forceinline__ void ldw256(const float* __restrict__ gW, int K, int kbase,
                                       int tid, float4* pre) {
#pragma unroll
    for (int p = 0; p < 4; p++) {
        int q = p*NTHR + tid;
        int row = q >> 6, c4 = q & 63;     // 64 float4 per 256-col row
        float4 v = make_float4(0.f, 0.f, 0.f, 0.f);
        if (kbase + row < K) v = *(const float4*)(gW + (size_t)(kbase+row)*256 + c4*4);
        pre[p] = v;
    }
}
__device__ __forceinline__ void stw256(float* sW, int tid, const float4* pre) {
#pragma unroll
    for (int p = 0; p < 4; p++) {
        int q = p*NTHR + tid;
        int row = q >> 6, c4 = q & 63;
        *(float4*)(sW + row*256 + c4*4) = pre[p];
    }
}

// ---------- GEMM: [64 x K] @ [K x 256] + bias, relu -> sOut (may alias sA) ----
// Thread (tm=tid>>5, tn=tid&31): rows m0..m0+7, cols tn*2 + 64*j (j=0..3).
// B loads: LDS.64 at 8B lane stride -> conflict-free. A loads: warp-uniform
// broadcast. One __syncthreads per k-tile (store into other buffer pre-sync).
// NOTE: caller must ensure sA cols [K, KT*ceil(K/KT)) are zeroed.
__device__ __forceinline__ void gemm256(const float* __restrict__ sA, int lda,
                                        const float* __restrict__ gW, int K,
                                        const float* __restrict__ gb,
                                        float* __restrict__ sOut, int ldo,
                                        float* sW, int tid)
{
    const int tm = tid >> 5, tn = tid & 31;
    const int m0 = tm * 8, n0 = tn * 2;
    ull acc[8][4];
#pragma unroll
    for (int i = 0; i < 8; i++)
#pragma unroll
        for (int j = 0; j < 4; j++) acc[i][j] = 0ull;

    const int nt = (K + KT - 1) / KT;
    float4 pre[4];
    ldw256(gW, K, 0, tid, pre);
    stw256(sW, tid, pre);
    __syncthreads();
    for (int kt = 0; kt < nt; kt++) {
        if (kt + 1 < nt) ldw256(gW, K, (kt+1)*KT, tid, pre);
        const float* Wb = sW + (kt & 1) * (KT*256);
        const float* Arow = sA + m0*lda + kt*KT;
#pragma unroll
        for (int kk = 0; kk < KT; kk++) {
            const ull* bp = (const ull*)(Wb + kk*256 + n0);
            ull w0 = bp[0], w1 = bp[32], w2 = bp[64], w3 = bp[96];
#pragma unroll
            for (int i = 0; i < 8; i++) {
                float a = Arow[i*lda + kk];
                ull aa = pack2(a, a);
                acc[i][0] = fma2(aa, w0, acc[i][0]);
                acc[i][1] = fma2(aa, w1, acc[i][1]);
                acc[i][2] = fma2(aa, w2, acc[i][2]);
                acc[i][3] = fma2(aa, w3, acc[i][3]);
            }
        }
        if (kt + 1 < nt) stw256(sW + ((kt+1) & 1)*(KT*256), tid, pre);
        __syncthreads();   // also guards overwrite of sA by the epilogue below
    }
    float2 bb[4];
#pragma unroll
    for (int j = 0; j < 4; j++) bb[j] = *(const float2*)(gb + n0 + 64*j);
#pragma unroll
    for (int i = 0; i < 8; i++) {
#pragma unroll
        for (int j = 0; j < 4; j++) {
            float2 v = unpack2(acc[i][j]);
            v.x = fmaxf(v.x + bb[j].x, 0.f);
            v.y = fmaxf(v.y + bb[j].y, 0.f);
            *(float2*)(sOut + (m0+i)*ldo + n0 + 64*j) = v;   // 8B lane stride: conflict-free
        }
    }
}

// ---------- GEMM: [64 x 256] @ [256 x 64] + bias, tanh -> global state ----------
__device__ __forceinline__ void gemm64_tanh(const float* __restrict__ sA, int lda,
                                            const float* __restrict__ gW,
                                            const float* __restrict__ gb,
                                            float* __restrict__ gOut,  // + b0*320 + nd*64
                                            float* sW, int tid)
{
    const int tm = tid >> 5, tn = tid & 31;
    const int m0 = tm * 8, n0 = tn * 2;
    ull acc[8];
#pragma unroll
    for (int i = 0; i < 8; i++) acc[i] = 0ull;

    const int nt = F0 / KT;                      // 16
    const int lrow = tid >> 4, lc4 = tid & 15;   // 16 float4 per 64-col row
    float4 pre = *(const float4*)(gW + (size_t)lrow*64 + lc4*4);
    *(float4*)(sW + lrow*64 + lc4*4) = pre;
    __syncthreads();
    for (int kt = 0; kt < nt; kt++) {
        if (kt + 1 < nt)
            pre = *(const float4*)(gW + (size_t)((kt+1)*KT + lrow)*64 + lc4*4);
        const float* Wb = sW + (kt & 1) * (KT*64);
        const float* Arow = sA + m0*lda + kt*KT;
#pragma unroll
        for (int kk = 0; kk < KT; kk++) {
            ull w = *(const ull*)(Wb + kk*64 + n0);
#pragma unroll
            for (int i = 0; i < 8; i++) {
                float a = Arow[i*lda + kk];
                acc[i] = fma2(pack2(a, a), w, acc[i]);
            }
        }
        if (kt + 1 < nt)
            *(float4*)(sW + ((kt+1) & 1)*(KT*64) + lrow*64 + lc4*4) = pre;
        __syncthreads();
    }
    const float2 bb = *(const float2*)(gb + n0);
#pragma unroll
    for (int i = 0; i < 8; i++) {
        float2 v = unpack2(acc[i]);
        float2 o;
        o.x = tanhf(v.x + bb.x);
        o.y = tanhf(v.y + bb.y);
        *(float2*)(gOut + (size_t)(m0+i)*STATE_STRIDE + n0) = o;
    }
}

// ---------- one recurrent timestep ----------
__global__ __launch_bounds__(NTHR, 2) void step_kernel(
    const float* __restrict__ x,
    const float* __restrict__ W1, const float* __restrict__ b1,
    const float* __restrict__ W2, const float* __restrict__ b2,
    const float* __restrict__ W3, const float* __restrict__ b3,
    int t)
{
    extern __shared__ float smem[];
    float* BUF = smem;                       // 64*260 (reused A/H1/H2)
    float* sW  = BUF + TILE_B*LDB;           // 2*16*256

    const int tid = threadIdx.x;
    const int nd  = blockIdx.y;
    const int b0  = blockIdx.x * TILE_B;
    const int rd  = t & 1, wr = rd ^ 1;
    const int p0  = c_par[nd][0], p1 = c_par[nd][1];
    const float* stp = g_state[rd];

    // assemble inp = [x_p0, x_p1, state_p0(64), state_p1(64)], zero-pad to col 144
    for (int i = tid; i < TILE_B * 2*FML; i += NTHR) {
        int m = i >> 7, c = i & 127;
        int p = (c < FML) ? p0 : p1;
        BUF[m*LDB + 2 + c] = stp[(size_t)(b0+m)*STATE_STRIDE + p*FML + (c & (FML-1))];
    }
    if (tid < TILE_B * 2) {
        int m = tid >> 1, w = tid & 1;
        int p = w ? p1 : p0;
        BUF[m*LDB + w] = x[(size_t)(b0+m)*(NNODE*T_TOT) + p*T_TOT + t];
    }
    for (int i = tid; i < TILE_B * 14; i += NTHR) {    // zero cols 130..143
        int m = i / 14, c = 130 + i % 14;
        BUF[m*LDB + c] = 0.f;
    }
    __syncthreads();

    gemm256(BUF, LDB, W1 + nd*(DIN*F0), DIN, b1 + nd*F0, BUF, LDB, sW, tid);
    __syncthreads();
    gemm256(BUF, LDB, W2 + nd*(F0*F0),  F0,  b2 + nd*F0, BUF, LDB, sW, tid);
    __syncthreads();
    gemm64_tanh(BUF, LDB, W3 + nd*(F0*FML), b3 + nd*FML,
                g_state[wr] + (size_t)b0*STATE_STRIDE + nd*FML, sW, tid);
}

// ---------- head GEMM (K=325) + deterministic BN partials ----------
__global__ __launch_bounds__(NTHR) void final1_kernel(
    const float* __restrict__ x,
    const float* __restrict__ Wo1, const float* __restrict__ bo1)
{
    extern __shared__ float smem[];
    float* sF = smem;                        // 64*336 (features, then H output)
    float* sW = sF + TILE_B*LDF;             // 2*16*256
    const int tid = threadIdx.x;
    const int b0  = blockIdx.x * TILE_B;
    const float* st = g_state[0];            // after t=127, state lives in buffer 0

    for (int i = tid; i < TILE_B*STATE_STRIDE; i += NTHR) {
        int m = i / STATE_STRIDE, c = i % STATE_STRIDE;
        sF[m*LDF + NNODE + c] = st[(size_t)(b0+m)*STATE_STRIDE + c];
    }
    for (int i = tid; i < TILE_B*NNODE; i += NTHR) {
        int m = i / NNODE, nn = i % NNODE;
        sF[m*LDF + nn] = x[(size_t)(b0+m)*(NNODE*T_TOT) + nn*T_TOT + (T_TOT-1)];
    }
    for (int i = tid; i < TILE_B*(LDF-KFEAT); i += NTHR) {   // zero cols 325..335
        int m = i / (LDF-KFEAT), c = KFEAT + i % (LDF-KFEAT);
        sF[m*LDF + c] = 0.f;
    }
    __syncthreads();

    gemm256(sF, LDF, Wo1, KFEAT, bo1, sF, LDF, sW, tid);
    __syncthreads();

    for (int i = tid; i < TILE_B*F0; i += NTHR) {
        int m = i >> 8, c = i & 255;
        g_h[(size_t)(b0+m)*F0 + c] = sF[m*LDF + c];
    }
    float s = 0.f, q = 0.f;
    for (int m = 0; m < TILE_B; m++) {
        float v = sF[m*LDF + tid];
        s += v; q += v*v;
    }
    g_psum[blockIdx.x*F0 + tid] = s;
    g_psq [blockIdx.x*F0 + tid] = q;
}

// ---------- fold BN stats into scale/shift (deterministic) ----------
__global__ void bn_kernel(const float* __restrict__ gamma, const float* __restrict__ beta) {
    int c = threadIdx.x;
    float s = 0.f, q = 0.f;
    for (int b = 0; b < (B_TOT/TILE_B); b++) { s += g_psum[b*F0 + c]; q += g_psq[b*F0 + c]; }
    float mu  = s * (1.f / B_TOT);
    float var = q * (1.f / B_TOT) - mu * mu;
    float rstd = rsqrtf(var + 1e-5f);
    float sc = gamma[c] * rstd;
    g_scale[c] = sc;
    g_shift[c] = beta[c] - mu * sc;
}

// ---------- normalize + 256x7 GEMM + softmax ----------
__global__ __launch_bounds__(NTHR) void final2_kernel(
    const float* __restrict__ Wo2, const float* __restrict__ bo2,
    float* __restrict__ out)
{
    __shared__ float sw2[F0*7];
    __shared__ float sb2[7];
    __shared__ float ssc[F0], ssh[F0];
    const int tid = threadIdx.x;
    for (int i = tid; i < F0*7; i += NTHR) sw2[i] = Wo2[i];
    if (tid < 7) sb2[tid] = bo2[tid];
    ssc[tid] = g_scale[tid];
    ssh[tid] = g_shift[tid];
    __syncthreads();

    const int warp = tid >> 5, lane = tid & 31;
    for (int r = 0; r < 16; r++) {                 // 64 blocks * 8 warps * 16 rows = 8192
        int b = blockIdx.x*128 + warp*16 + r;
        float a0=0,a1=0,a2=0,a3=0,a4=0,a5=0,a6=0;
        const float* hp = g_h + (size_t)b*F0;
#pragma unroll
        for (int kk = 0; kk < 8; kk++) {
            int k = kk*32 + lane;
            float hv = hp[k]*ssc[k] + ssh[k];
            const float* wr = sw2 + k*7;
            a0 += hv*wr[0]; a1 += hv*wr[1]; a2 += hv*wr[2]; a3 += hv*wr[3];
            a4 += hv*wr[4]; a5 += hv*wr[5]; a6 += hv*wr[6];
        }
#pragma unroll
        for (int off = 16; off; off >>= 1) {
            a0 += __shfl_down_sync(0xffffffffu, a0, off);
            a1 += __shfl_down_sync(0xffffffffu, a1, off);
            a2 += __shfl_down_sync(0xffffffffu, a2, off);
            a3 += __shfl_down_sync(0xffffffffu, a3, off);
            a4 += __shfl_down_sync(0xffffffffu, a4, off);
            a5 += __shfl_down_sync(0xffffffffu, a5, off);
            a6 += __shfl_down_sync(0xffffffffu, a6, off);
        }
        if (lane == 0) {
            float l[7] = { a0+sb2[0], a1+sb2[1], a2+sb2[2], a3+sb2[3],
                           a4+sb2[4], a5+sb2[5], a6+sb2[6] };
            float mx = l[0];
#pragma unroll
            for (int j = 1; j < 7; j++) mx = fmaxf(mx, l[j]);
            float e[7], se = 0.f;
#pragma unroll
            for (int j = 0; j < 7; j++) { e[j] = expf(l[j] - mx); se += e[j]; }
            float inv = 1.f / se;
#pragma unroll
            for (int j = 0; j < 7; j++) out[(size_t)b*7 + j] = e[j]*inv;
        }
    }
}

__global__ void zero_state_kernel() {
    size_t n = (size_t)B_TOT*STATE_STRIDE;
    for (size_t i = blockIdx.x*(size_t)blockDim.x + threadIdx.x; i < n;
         i += (size_t)gridDim.x*blockDim.x)
        g_state[0][i] = 0.f;
}

extern "C" void kernel_launch(void* const* d_in, const int* in_sizes, int n_in,
                              void* d_out, int out_size)
{
    (void)in_sizes; (void)n_in; (void)out_size;
    const float* x     = (const float*)d_in[0];
    const float* W1    = (const float*)d_in[1];
    const float* b1    = (const float*)d_in[2];
    const float* W2    = (const float*)d_in[3];
    const float* b2    = (const float*)d_in[4];
    const float* W3    = (const float*)d_in[5];
    const float* b3    = (const float*)d_in[6];
    const float* Wo1   = (const float*)d_in[7];
    const float* bo1   = (const float*)d_in[8];
    const float* gamma = (const float*)d_in[9];
    const float* beta  = (const float*)d_in[10];
    const float* Wo2   = (const float*)d_in[11];
    const float* bo2   = (const float*)d_in[12];
    float* out = (float*)d_out;

    const int STEP_SMEM = (TILE_B*LDB + 2*KT*256) * (int)sizeof(float);  // 99,328 B
    const int F1_SMEM   = (TILE_B*LDF + 2*KT*256) * (int)sizeof(float);  // 118,784 B
    cudaFuncSetAttribute(step_kernel,   cudaFuncAttributeMaxDynamicSharedMemorySize, STEP_SMEM);
    cudaFuncSetAttribute(final1_kernel, cudaFuncAttributeMaxDynamicSharedMemorySize, F1_SMEM);

    zero_state_kernel<<<512, 256>>>();

    dim3 sgrid(B_TOT/TILE_B, NNODE);
    for (int t = 0; t < T_TOT; t++)
        step_kernel<<<sgrid, NTHR, STEP_SMEM>>>(x, W1, b1, W2, b2, W3, b3, t);

    final1_kernel<<<B_TOT/TILE_B, NTHR, F1_SMEM>>>(x, Wo1, bo1);
    bn_kernel<<<1, F0>>>(gamma, beta);
    final2_kernel<<<64, NTHR>>>(Wo2, bo2, out);
}

// round 6
// speedup vs baseline: 1.8947x; 1.6720x over previous
#include <cuda_runtime.h>
#include <cuda_fp16.h>
#include <math.h>
#include <stdint.h>

typedef unsigned long long ull;

#define B_TOT 8192
#define T_TOT 128
#define NNODE 5
#define FML   64
#define F0    256
#define DIN   130
#define KFEAT 325
#define TILE_B 64
#define NTHR   256
#define KT     16
#define LDF    336

#define SM_M   128        // batch rows per step CTA
#define STHR   512        // step kernel threads
#define LDA    264        // A row pitch in halves (528B)
#define LDB    264        // B chunk row pitch (L1/L2)
#define LDB3   72         // B chunk row pitch (L3)
#define K1     144        // padded K of layer1

__constant__ int c_par[NNODE][2] = {{3,4},{0,4},{0,1},{1,2},{2,3}};

// ---------------- device scratch ----------------
__device__ float g_state2[2][NNODE][B_TOT][FML];
__device__ float g_h[(size_t)B_TOT*F0];
__device__ float g_psum[(B_TOT/TILE_B)*F0];
__device__ float g_psq [(B_TOT/TILE_B)*F0];
__device__ float g_scale[F0], g_shift[F0];
// fp16-split weights, chunked [nd][chunk][16][pitch]
__device__ __half g_W1h[5*9*16*LDB],  g_W1l[5*9*16*LDB];
__device__ __half g_W2h[5*16*16*LDB], g_W2l[5*16*16*LDB];
__device__ __half g_W3h[5*16*16*LDB3],g_W3l[5*16*16*LDB3];

// ---------------- f32x2 helpers (final head GEMM) ----------------
__device__ __forceinline__ ull fma2(ull a, ull b, ull c) {
    ull d; asm("fma.rn.f32x2 %0, %1, %2, %3;" : "=l"(d) : "l"(a), "l"(b), "l"(c)); return d;
}
__device__ __forceinline__ ull pack2(float x, float y) {
    ull d; asm("mov.b64 %0, {%1, %2};" : "=l"(d) : "f"(x), "f"(y)); return d;
}
__device__ __forceinline__ float2 unpack2(ull v) {
    float2 r; asm("mov.b64 {%0, %1}, %2;" : "=f"(r.x), "=f"(r.y) : "l"(v)); return r;
}

// ---------------- tensor-core primitives (baseline PTX, sm_80+) ----------------
__device__ __forceinline__ uint32_t smem_to_u32(const void* p) {
    uint32_t a; asm("{ .reg .u64 t; cvta.to.shared.u64 t, %1; cvt.u32.u64 %0, t; }" : "=r"(a) : "l"(p)); return a;
}
__device__ __forceinline__ void ldsm4(uint32_t a, uint32_t* r) {
    asm volatile("ldmatrix.sync.aligned.m8n8.x4.shared.b16 {%0,%1,%2,%3}, [%4];"
        : "=r"(r[0]), "=r"(r[1]), "=r"(r[2]), "=r"(r[3]) : "r"(a));
}
__device__ __forceinline__ void ldsm4t(uint32_t a, uint32_t* r) {
    asm volatile("ldmatrix.sync.aligned.m8n8.x4.trans.shared.b16 {%0,%1,%2,%3}, [%4];"
        : "=r"(r[0]), "=r"(r[1]), "=r"(r[2]), "=r"(r[3]) : "r"(a));
}
__device__ __forceinline__ void mma16816(float* c, const uint32_t* a, uint32_t b0, uint32_t b1) {
    asm volatile("mma.sync.aligned.m16n8k16.row.col.f32.f16.f16.f32 "
        "{%0,%1,%2,%3}, {%4,%5,%6,%7}, {%8,%9}, {%0,%1,%2,%3};"
        : "+f"(c[0]), "+f"(c[1]), "+f"(c[2]), "+f"(c[3])
        : "r"(a[0]), "r"(a[1]), "r"(a[2]), "r"(a[3]), "r"(b0), "r"(b1));
}
__device__ __forceinline__ void cp16(uint32_t dst, const void* src) {
    asm volatile("cp.async.cg.shared.global [%0], [%1], 16;" :: "r"(dst), "l"(src));
}
#define CP_COMMIT() asm volatile("cp.async.commit_group;" ::: "memory")
#define CP_WAIT0()  asm volatile("cp.async.wait_group 0;" ::: "memory")

// smem byte offsets
#define OFF_AH   0
#define OFF_AL   67584                 // 128*264*2
#define OFF_B    135168                // 2 buffers x (Bh 8448 | Bl 8448)
#define BUF_STRIDE 16896
#define OFF_BIAS 168960                // b1 @+0(1024B), b2 @+1024, b3 @+2048(256B)
#define STEP_SMEM (168960 + 2304)

// ---------------- weight prep: transpose-to-chunks + fp16 split ----------------
__global__ void prep_kernel(const float* __restrict__ W1, const float* __restrict__ W2,
                            const float* __restrict__ W3) {
    int i0 = blockIdx.x*blockDim.x + threadIdx.x, gs = gridDim.x*blockDim.x;
    for (int i = i0; i < 5*9*16*LDB; i += gs) {        // W1: [nd][9][16][264]
        int nd = i/(9*16*LDB), r = i%(9*16*LDB);
        int kc = r/(16*LDB), q = r%(16*LDB), kr = q/LDB, n = q%LDB;
        int k = kc*16 + kr;
        float v = (k < DIN && n < F0) ? W1[((size_t)nd*DIN + k)*F0 + n] : 0.f;
        __half h = __float2half_rn(v);
        g_W1h[i] = h; g_W1l[i] = __float2half_rn(v - __half2float(h));
    }
    for (int i = i0; i < 5*16*16*LDB; i += gs) {       // W2: [nd][16][16][264]
        int nd = i/(16*16*LDB), r = i%(16*16*LDB);
        int kc = r/(16*LDB), q = r%(16*LDB), kr = q/LDB, n = q%LDB;
        int k = kc*16 + kr;
        float v = (n < F0) ? W2[((size_t)nd*F0 + k)*F0 + n] : 0.f;
        __half h = __float2half_rn(v);
        g_W2h[i] = h; g_W2l[i] = __float2half_rn(v - __half2float(h));
    }
    for (int i = i0; i < 5*16*16*LDB3; i += gs) {      // W3: [nd][16][16][72]
        int nd = i/(16*16*LDB3), r = i%(16*16*LDB3);
        int kc = r/(16*LDB3), q = r%(16*LDB3), kr = q/LDB3, n = q%LDB3;
        int k = kc*16 + kr;
        float v = (n < FML) ? W3[((size_t)nd*F0 + k)*FML + n] : 0.f;
        __half h = __float2half_rn(v);
        g_W3h[i] = h; g_W3l[i] = __float2half_rn(v - __half2float(h));
    }
}

// B chunk loader: linear 16B copies, one commit group. n16 = 16B units per part.
__device__ __forceinline__ void loadB(const __half* gh, const __half* gl, int n16,
                                      uint32_t dst, int tid) {
    for (int j = tid; j < n16; j += STHR) cp16(dst + j*16, (const char*)gh + j*16);
    for (int j = tid; j < n16; j += STHR) cp16(dst + 8448 + j*16, (const char*)gl + j*16);
    CP_COMMIT();
}

// compute one k16 chunk, N=256 (warp tile 32x64)
__device__ __forceinline__ void chunk256(uint32_t aHaddr, uint32_t aLaddr,
                                         uint32_t bBase, float (&acc)[2][8][4]) {
    uint32_t ah[2][4], al[2][4];
    ldsm4(aHaddr, ah[0]); ldsm4(aHaddr + 16*LDA*2, ah[1]);
    ldsm4(aLaddr, al[0]); ldsm4(aLaddr + 16*LDA*2, al[1]);
#pragma unroll
    for (int g = 0; g < 4; g++) {
        uint32_t bh[4], bl[4];
        ldsm4t(bBase + g*32, bh);
        ldsm4t(bBase + 8448 + g*32, bl);
#pragma unroll
        for (int mf = 0; mf < 2; mf++)
#pragma unroll
            for (int s = 0; s < 2; s++) {
                float* c = acc[mf][2*g + s];
                mma16816(c, ah[mf], bh[2*s], bh[2*s+1]);
                mma16816(c, ah[mf], bl[2*s], bl[2*s+1]);
                mma16816(c, al[mf], bh[2*s], bh[2*s+1]);
            }
    }
}
// compute one k16 chunk, N=64 (warp tile 32x16)
__device__ __forceinline__ void chunk64(uint32_t aHaddr, uint32_t aLaddr,
                                        uint32_t bBase, float (&acc)[2][8][4]) {
    uint32_t ah[2][4], al[2][4], bh[4], bl[4];
    ldsm4(aHaddr, ah[0]); ldsm4(aHaddr + 16*LDA*2, ah[1]);
    ldsm4(aLaddr, al[0]); ldsm4(aLaddr + 16*LDA*2, al[1]);
    ldsm4t(bBase, bh);
    ldsm4t(bBase + 8448, bl);
#pragma unroll
    for (int mf = 0; mf < 2; mf++)
#pragma unroll
        for (int s = 0; s < 2; s++) {
            float* c = acc[mf][s];
            mma16816(c, ah[mf], bh[2*s], bh[2*s+1]);
            mma16816(c, ah[mf], bl[2*s], bl[2*s+1]);
            mma16816(c, al[mf], bh[2*s], bh[2*s+1]);
        }
}

// epilogue: relu(acc+bias) -> fp16 split -> store into A buffers; zero acc
__device__ __forceinline__ void epiA(float (&acc)[2][8][4], const float* sb,
                                     char* sm, int m0, int n0, int lane) {
#pragma unroll
    for (int mf = 0; mf < 2; mf++)
#pragma unroll
        for (int nf = 0; nf < 8; nf++) {
            int col = n0 + 8*nf + (lane & 3)*2;
            float bx = sb[col], by = sb[col+1];
            int r0 = m0 + 16*mf + (lane >> 2);
            float v00 = fmaxf(acc[mf][nf][0] + bx, 0.f);
            float v01 = fmaxf(acc[mf][nf][1] + by, 0.f);
            float v10 = fmaxf(acc[mf][nf][2] + bx, 0.f);
            float v11 = fmaxf(acc[mf][nf][3] + by, 0.f);
            __half h00 = __float2half_rn(v00), h01 = __float2half_rn(v01);
            __half h10 = __float2half_rn(v10), h11 = __float2half_rn(v11);
            *(__half2*)(sm + OFF_AH + ((size_t)r0*LDA + col)*2)     = __halves2half2(h00, h01);
            *(__half2*)(sm + OFF_AH + ((size_t)(r0+8)*LDA + col)*2) = __halves2half2(h10, h11);
            *(__half2*)(sm + OFF_AL + ((size_t)r0*LDA + col)*2) =
                __halves2half2(__float2half_rn(v00 - __half2float(h00)),
                               __float2half_rn(v01 - __half2float(h01)));
            *(__half2*)(sm + OFF_AL + ((size_t)(r0+8)*LDA + col)*2) =
                __halves2half2(__float2half_rn(v10 - __half2float(h10)),
                               __float2half_rn(v11 - __half2float(h11)));
            acc[mf][nf][0] = acc[mf][nf][1] = acc[mf][nf][2] = acc[mf][nf][3] = 0.f;
        }
}

// ---------------- one recurrent timestep (mma.sync tensor path) ----------------
__global__ void __launch_bounds__(STHR, 1) step3_kernel(
    const float* __restrict__ x,
    const float* __restrict__ b1, const float* __restrict__ b2,
    const float* __restrict__ b3, int t)
{
    extern __shared__ char sm[];
    const uint32_t smb = smem_to_u32(sm);

    const int tid = threadIdx.x, lane = tid & 31, wid = tid >> 5;
    const int mw = wid >> 2, nwc = wid & 3;      // warp grid 4x4
    const int m0 = mw * 32;
    const int n0 = nwc * 64;                     // N=256 layers
    const int n03 = nwc * 16;                    // N=64 layer
    const int nd = blockIdx.y;
    const int b0 = blockIdx.x * SM_M;
    const int rd = t & 1, wrp = rd ^ 1;
    const int p0 = c_par[nd][0], p1 = c_par[nd][1];

    float* sB1 = (float*)(sm + OFF_BIAS);
    float* sB2 = (float*)(sm + OFF_BIAS + 1024);
    float* sB3 = (float*)(sm + OFF_BIAS + 2048);
    if (tid < 256) { sB1[tid] = b1[nd*F0 + tid]; sB2[tid] = b2[nd*F0 + tid]; }
    if (tid < 64)  sB3[tid] = b3[nd*FML + tid];

    // per-thread ldmatrix base addresses
    const int rowoff = ((lane >> 3) & 1)*8 + (lane & 7);
    const int koffA  = (lane >> 4)*8;
    const uint32_t aH0 = smb + OFF_AH + (((uint32_t)(m0 + rowoff))*LDA + koffA)*2;
    const uint32_t aL0 = smb + OFF_AL + (((uint32_t)(m0 + rowoff))*LDA + koffA)*2;
    const uint32_t bRow = ((lane >> 3) & 1)*8 + (lane & 7);
    const uint32_t bCol = (uint32_t)(lane >> 4)*8;
    const uint32_t bOffL12 = (bRow*LDB + n0 + bCol)*2;
    const uint32_t bOffL3  = (bRow*LDB3 + n03 + bCol)*2;
    const uint32_t bufA[2] = { smb + OFF_B, smb + OFF_B + BUF_STRIDE };

    float acc[2][8][4];
#pragma unroll
    for (int a = 0; a < 2; a++)
#pragma unroll
        for (int b = 0; b < 8; b++)
#pragma unroll
            for (int c = 0; c < 4; c++) acc[a][b][c] = 0.f;

    // prefetch L1 chunk0 into buf0
    loadB(g_W1h + ((size_t)nd*9)*16*LDB, g_W1l + ((size_t)nd*9)*16*LDB, 528, bufA[0], tid);

    // gather L1 input A (fp16 split): cols 0..143 (130..143 zero)
    {
        const float* Sp0 = &g_state2[rd][p0][0][0];
        const float* Sp1 = &g_state2[rd][p1][0][0];
        for (int i = tid; i < SM_M*K1; i += STHR) {
            int r = i / K1, c = i % K1;
            float v = 0.f;
            if (c < 2)        v = x[(size_t)(b0 + r)*(NNODE*T_TOT) + (c ? p1 : p0)*T_TOT + t];
            else if (c < 66)  v = Sp0[(size_t)(b0 + r)*FML + (c - 2)];
            else if (c < 130) v = Sp1[(size_t)(b0 + r)*FML + (c - 66)];
            __half h = __float2half_rn(v);
            *(__half*)(sm + OFF_AH + ((size_t)r*LDA + c)*2) = h;
            *(__half*)(sm + OFF_AL + ((size_t)r*LDA + c)*2) = __float2half_rn(v - __half2float(h));
        }
    }

    // ===== LAYER 1: 9 chunks, phase 0 =====
    for (int kc = 0; kc < 9; kc++) {
        CP_WAIT0();
        __syncthreads();
        if (kc + 1 < 9)
            loadB(g_W1h + ((size_t)nd*9 + kc + 1)*16*LDB,
                  g_W1l + ((size_t)nd*9 + kc + 1)*16*LDB, 528, bufA[(kc+1)&1], tid);
        chunk256(aH0 + kc*32, aL0 + kc*32, bufA[kc&1] + bOffL12, acc);
    }
    // prefetch L2 chunk0 into buf1 (free: last read was chunk7)
    loadB(g_W2h + ((size_t)nd*16)*16*LDB, g_W2l + ((size_t)nd*16)*16*LDB, 528, bufA[1], tid);
    __syncthreads();
    epiA(acc, sB1, sm, m0, n0, lane);

    // ===== LAYER 2: 16 chunks, phase 1 =====
    for (int kc = 0; kc < 16; kc++) {
        CP_WAIT0();
        __syncthreads();
        if (kc + 1 < 16)
            loadB(g_W2h + ((size_t)nd*16 + kc + 1)*16*LDB,
                  g_W2l + ((size_t)nd*16 + kc + 1)*16*LDB, 528, bufA[kc&1], tid);
        chunk256(aH0 + kc*32, aL0 + kc*32, bufA[(kc+1)&1] + bOffL12, acc);
    }
    // prefetch L3 chunk0 into buf1 (free: last read was chunk14)
    loadB(g_W3h + ((size_t)nd*16)*16*LDB3, g_W3l + ((size_t)nd*16)*16*LDB3, 144, bufA[1], tid);
    __syncthreads();
    epiA(acc, sB2, sm, m0, n0, lane);

    // ===== LAYER 3: 16 chunks, N=64, phase 1 =====
    for (int kc = 0; kc < 16; kc++) {
        CP_WAIT0();
        __syncthreads();
        if (kc + 1 < 16)
            loadB(g_W3h + ((size_t)nd*16 + kc + 1)*16*LDB3,
                  g_W3l + ((size_t)nd*16 + kc + 1)*16*LDB3, 144, bufA[kc&1], tid);
        chunk64(aH0 + kc*32, aL0 + kc*32, bufA[(kc+1)&1] + bOffL3, acc);
    }

    // epilogue: state = tanh(acc + b3)
    float* gS = &g_state2[wrp][nd][0][0];
#pragma unroll
    for (int mf = 0; mf < 2; mf++)
#pragma unroll
        for (int nf = 0; nf < 2; nf++) {
            int col = n03 + 8*nf + (lane & 3)*2;
            float bx = sB3[col], by = sB3[col+1];
            int r0 = m0 + 16*mf + (lane >> 2);
            float2 o0, o1;
            o0.x = tanhf(acc[mf][nf][0] + bx);
            o0.y = tanhf(acc[mf][nf][1] + by);
            o1.x = tanhf(acc[mf][nf][2] + bx);
            o1.y = tanhf(acc[mf][nf][3] + by);
            *(float2*)(gS + (size_t)(b0 + r0)*FML + col)     = o0;
            *(float2*)(gS + (size_t)(b0 + r0 + 8)*FML + col) = o1;
        }
}

// ---------------- final head (SIMT, unchanged logic) ----------------
__device__ __forceinline__ void ldw256(const float* __restrict__ gW, int K, int kbase,
                                       int tid, float4* pre) {
#pragma unroll
    for (int p = 0; p < 4; p++) {
        int q = p*NTHR + tid, row = q >> 6, c4 = q & 63;
        float4 v = make_float4(0.f, 0.f, 0.f, 0.f);
        if (kbase + row < K) v = *(const float4*)(gW + (size_t)(kbase+row)*256 + c4*4);
        pre[p] = v;
    }
}
__device__ __forceinline__ void stw256(float* sW, int tid, const float4* pre) {
#pragma unroll
    for (int p = 0; p < 4; p++) {
        int q = p*NTHR + tid, row = q >> 6, c4 = q & 63;
        *(float4*)(sW + row*256 + c4*4) = pre[p];
    }
}
__device__ __forceinline__ void gemm256(const float* __restrict__ sA, int lda,
                                        const float* __restrict__ gW, int K,
                                        const float* __restrict__ gb,
                                        float* __restrict__ sOut, int ldo,
                                        float* sW, int tid)
{
    const int tm = tid >> 5, tn = tid & 31;
    const int m0 = tm * 8, n0 = tn * 2;
    ull acc[8][4];
#pragma unroll
    for (int i = 0; i < 8; i++)
#pragma unroll
        for (int j = 0; j < 4; j++) acc[i][j] = 0ull;
    const int nt = (K + KT - 1) / KT;
    float4 pre[4];
    ldw256(gW, K, 0, tid, pre);
    stw256(sW, tid, pre);
    __syncthreads();
    for (int kt = 0; kt < nt; kt++) {
        if (kt + 1 < nt) ldw256(gW, K, (kt+1)*KT, tid, pre);
        const float* Wb = sW + (kt & 1) * (KT*256);
        const float* Arow = sA + m0*lda + kt*KT;
#pragma unroll
        for (int kk = 0; kk < KT; kk++) {
            const ull* bp = (const ull*)(Wb + kk*256 + n0);
            ull w0 = bp[0], w1 = bp[32], w2 = bp[64], w3 = bp[96];
#pragma unroll
            for (int i = 0; i < 8; i++) {
                float a = Arow[i*lda + kk];
                ull aa = pack2(a, a);
                acc[i][0] = fma2(aa, w0, acc[i][0]);
                acc[i][1] = fma2(aa, w1, acc[i][1]);
                acc[i][2] = fma2(aa, w2, acc[i][2]);
                acc[i][3] = fma2(aa, w3, acc[i][3]);
            }
        }
        if (kt + 1 < nt) stw256(sW + ((kt+1) & 1)*(KT*256), tid, pre);
        __syncthreads();
    }
    float2 bb[4];
#pragma unroll
    for (int j = 0; j < 4; j++) bb[j] = *(const float2*)(gb + n0 + 64*j);
#pragma unroll
    for (int i = 0; i < 8; i++)
#pragma unroll
        for (int j = 0; j < 4; j++) {
            float2 v = unpack2(acc[i][j]);
            v.x = fmaxf(v.x + bb[j].x, 0.f);
            v.y = fmaxf(v.y + bb[j].y, 0.f);
            *(float2*)(sOut + (m0+i)*ldo + n0 + 64*j) = v;
        }
}

__global__ __launch_bounds__(NTHR) void final1_kernel(
    const float* __restrict__ x,
    const float* __restrict__ Wo1, const float* __restrict__ bo1)
{
    extern __shared__ float smem[];
    float* sF = smem;
    float* sW = sF + TILE_B*LDF;
    const int tid = threadIdx.x;
    const int b0  = blockIdx.x * TILE_B;
    const float* st = &g_state2[0][0][0][0];

    for (int i = tid; i < TILE_B*320; i += NTHR) {
        int m = i / 320, c = i % 320;
        sF[m*LDF + NNODE + c] = st[((size_t)(c >> 6)*B_TOT + (b0+m))*FML + (c & 63)];
    }
    for (int i = tid; i < TILE_B*NNODE; i += NTHR) {
        int m = i / NNODE, nn = i % NNODE;
        sF[m*LDF + nn] = x[(size_t)(b0+m)*(NNODE*T_TOT) + nn*T_TOT + (T_TOT-1)];
    }
    for (int i = tid; i < TILE_B*(LDF-KFEAT); i += NTHR) {
        int m = i / (LDF-KFEAT), c = KFEAT + i % (LDF-KFEAT);
        sF[m*LDF + c] = 0.f;
    }
    __syncthreads();
    gemm256(sF, LDF, Wo1, KFEAT, bo1, sF, LDF, sW, tid);
    __syncthreads();
    for (int i = tid; i < TILE_B*F0; i += NTHR) {
        int m = i >> 8, c = i & 255;
        g_h[(size_t)(b0+m)*F0 + c] = sF[m*LDF + c];
    }
    float s = 0.f, q = 0.f;
    for (int m = 0; m < TILE_B; m++) {
        float v = sF[m*LDF + tid];
        s += v; q += v*v;
    }
    g_psum[blockIdx.x*F0 + tid] = s;
    g_psq [blockIdx.x*F0 + tid] = q;
}

__global__ void bn_kernel(const float* __restrict__ gamma, const float* __restrict__ beta) {
    int c = threadIdx.x;
    float s = 0.f, q = 0.f;
    for (int b = 0; b < (B_TOT/TILE_B); b++) { s += g_psum[b*F0 + c]; q += g_psq[b*F0 + c]; }
    float mu  = s * (1.f / B_TOT);
    float var = q * (1.f / B_TOT) - mu * mu;
    float sc = gamma[c] * rsqrtf(var + 1e-5f);
    g_scale[c] = sc;
    g_shift[c] = beta[c] - mu * sc;
}

__global__ __launch_bounds__(NTHR) void final2_kernel(
    const float* __restrict__ Wo2, const float* __restrict__ bo2, float* __restrict__ out)
{
    __shared__ float sw2[F0*7], sb2[7], ssc[F0], ssh[F0];
    const int tid = threadIdx.x;
    for (int i = tid; i < F0*7; i += NTHR) sw2[i] = Wo2[i];
    if (tid < 7) sb2[tid] = bo2[tid];
    ssc[tid] = g_scale[tid];
    ssh[tid] = g_shift[tid];
    __syncthreads();
    const int warp = tid >> 5, lane = tid & 31;
    for (int r = 0; r < 16; r++) {
        int b = blockIdx.x*128 + warp*16 + r;
        float a0=0,a1=0,a2=0,a3=0,a4=0,a5=0,a6=0;
        const float* hp = g_h + (size_t)b*F0;
#pragma unroll
        for (int kk = 0; kk < 8; kk++) {
            int k = kk*32 + lane;
            float hv = hp[k]*ssc[k] + ssh[k];
            const float* wrp2 = sw2 + k*7;
            a0 += hv*wrp2[0]; a1 += hv*wrp2[1]; a2 += hv*wrp2[2]; a3 += hv*wrp2[3];
            a4 += hv*wrp2[4]; a5 += hv*wrp2[5]; a6 += hv*wrp2[6];
        }
#pragma unroll
        for (int off = 16; off; off >>= 1) {
            a0 += __shfl_down_sync(0xffffffffu, a0, off);
            a1 += __shfl_down_sync(0xffffffffu, a1, off);
            a2 += __shfl_down_sync(0xffffffffu, a2, off);
            a3 += __shfl_down_sync(0xffffffffu, a3, off);
            a4 += __shfl_down_sync(0xffffffffu, a4, off);
            a5 += __shfl_down_sync(0xffffffffu, a5, off);
            a6 += __shfl_down_sync(0xffffffffu, a6, off);
        }
        if (lane == 0) {
            float l[7] = { a0+sb2[0], a1+sb2[1], a2+sb2[2], a3+sb2[3], a4+sb2[4], a5+sb2[5], a6+sb2[6] };
            float mx = l[0];
#pragma unroll
            for (int j = 1; j < 7; j++) mx = fmaxf(mx, l[j]);
            float e[7], se = 0.f;
#pragma unroll
            for (int j = 0; j < 7; j++) { e[j] = expf(l[j] - mx); se += e[j]; }
            float inv = 1.f / se;
#pragma unroll
            for (int j = 0; j < 7; j++) out[(size_t)b*7 + j] = e[j]*inv;
        }
    }
}

__global__ void zero_state_kernel() {
    size_t n = (size_t)NNODE*B_TOT*FML;
    float* p = &g_state2[0][0][0][0];
    for (size_t i = blockIdx.x*(size_t)blockDim.x + threadIdx.x; i < n;
         i += (size_t)gridDim.x*blockDim.x) p[i] = 0.f;
}

extern "C" void kernel_launch(void* const* d_in, const int* in_sizes, int n_in,
                              void* d_out, int out_size)
{
    (void)in_sizes; (void)n_in; (void)out_size;
    const float* x     = (const float*)d_in[0];
    const float* W1    = (const float*)d_in[1];
    const float* b1    = (const float*)d_in[2];
    const float* W2    = (const float*)d_in[3];
    const float* b2    = (const float*)d_in[4];
    const float* W3    = (const float*)d_in[5];
    const float* b3    = (const float*)d_in[6];
    const float* Wo1   = (const float*)d_in[7];
    const float* bo1   = (const float*)d_in[8];
    const float* gamma = (const float*)d_in[9];
    const float* beta  = (const float*)d_in[10];
    const float* Wo2   = (const float*)d_in[11];
    const float* bo2   = (const float*)d_in[12];
    float* out = (float*)d_out;

    const int F1_SMEM = (TILE_B*LDF + 2*KT*256) * (int)sizeof(float);
    cudaFuncSetAttribute(step3_kernel,  cudaFuncAttributeMaxDynamicSharedMemorySize, STEP_SMEM);
    cudaFuncSetAttribute(final1_kernel, cudaFuncAttributeMaxDynamicSharedMemorySize, F1_SMEM);

    prep_kernel<<<512, 256>>>(W1, W2, W3);
    zero_state_kernel<<<512, 256>>>();

    dim3 sgrid(B_TOT/SM_M, NNODE);
    for (int t = 0; t < T_TOT; t++)
        step3_kernel<<<sgrid, STHR, STEP_SMEM>>>(x, b1, b2, b3, t);

    final1_kernel<<<B_TOT/TILE_B, NTHR, F1_SMEM>>>(x, Wo1, bo1);
    bn_kernel<<<1, F0>>>(gamma, beta);
    final2_kernel<<<64, NTHR>>>(Wo2, bo2, out);
}

// round 7
// speedup vs baseline: 2.3862x; 1.2594x over previous
#include <cuda_runtime.h>
#include <cuda_fp16.h>
#include <math.h>
#include <stdint.h>

typedef unsigned long long ull;

#define B_TOT 8192
#define T_TOT 128
#define NNODE 5
#define FML   64
#define F0    256
#define DIN   130
#define KFEAT 325
#define TILE_B 64
#define NTHR   256
#define KT     16
#define LDF    336

#define SM_M   64         // batch rows per step CTA (2 CTAs/SM)
#define STHR   256        // step kernel threads (8 warps: 2 M-bands x 4 N-cols)
#define LDA    264        // A row pitch in halves (528B)
#define LDB    264        // B chunk row pitch (L1/L2)
#define LDB3   72         // B chunk row pitch (L3)
#define K1     144        // padded K of layer1

__constant__ int c_par[NNODE][2] = {{3,4},{0,4},{0,1},{1,2},{2,3}};

// ---------------- device scratch ----------------
__device__ float g_state2[2][NNODE][B_TOT][FML];
__device__ float g_h[(size_t)B_TOT*F0];
__device__ float g_psum[(B_TOT/TILE_B)*F0];
__device__ float g_psq [(B_TOT/TILE_B)*F0];
__device__ float g_scale[F0], g_shift[F0];
// fp16-split weights, chunked [nd][chunk][16][pitch]
__device__ __half g_W1h[5*9*16*LDB],  g_W1l[5*9*16*LDB];
__device__ __half g_W2h[5*16*16*LDB], g_W2l[5*16*16*LDB];
__device__ __half g_W3h[5*16*16*LDB3],g_W3l[5*16*16*LDB3];

// ---------------- f32x2 helpers (final head GEMM) ----------------
__device__ __forceinline__ ull fma2(ull a, ull b, ull c) {
    ull d; asm("fma.rn.f32x2 %0, %1, %2, %3;" : "=l"(d) : "l"(a), "l"(b), "l"(c)); return d;
}
__device__ __forceinline__ ull pack2(float x, float y) {
    ull d; asm("mov.b64 %0, {%1, %2};" : "=l"(d) : "f"(x), "f"(y)); return d;
}
__device__ __forceinline__ float2 unpack2(ull v) {
    float2 r; asm("mov.b64 {%0, %1}, %2;" : "=f"(r.x), "=f"(r.y) : "l"(v)); return r;
}

// ---------------- tensor-core primitives (baseline PTX, sm_80+) ----------------
__device__ __forceinline__ uint32_t smem_to_u32(const void* p) {
    uint32_t a; asm("{ .reg .u64 t; cvta.to.shared.u64 t, %1; cvt.u32.u64 %0, t; }" : "=r"(a) : "l"(p)); return a;
}
__device__ __forceinline__ void ldsm4(uint32_t a, uint32_t* r) {
    asm volatile("ldmatrix.sync.aligned.m8n8.x4.shared.b16 {%0,%1,%2,%3}, [%4];"
        : "=r"(r[0]), "=r"(r[1]), "=r"(r[2]), "=r"(r[3]) : "r"(a));
}
__device__ __forceinline__ void ldsm4t(uint32_t a, uint32_t* r) {
    asm volatile("ldmatrix.sync.aligned.m8n8.x4.trans.shared.b16 {%0,%1,%2,%3}, [%4];"
        : "=r"(r[0]), "=r"(r[1]), "=r"(r[2]), "=r"(r[3]) : "r"(a));
}
__device__ __forceinline__ void mma16816(float* c, const uint32_t* a, uint32_t b0, uint32_t b1) {
    asm volatile("mma.sync.aligned.m16n8k16.row.col.f32.f16.f16.f32 "
        "{%0,%1,%2,%3}, {%4,%5,%6,%7}, {%8,%9}, {%0,%1,%2,%3};"
        : "+f"(c[0]), "+f"(c[1]), "+f"(c[2]), "+f"(c[3])
        : "r"(a[0]), "r"(a[1]), "r"(a[2]), "r"(a[3]), "r"(b0), "r"(b1));
}
__device__ __forceinline__ void cp16(uint32_t dst, const void* src) {
    asm volatile("cp.async.cg.shared.global [%0], [%1], 16;" :: "r"(dst), "l"(src));
}
#define CP_COMMIT() asm volatile("cp.async.commit_group;" ::: "memory")
#define CP_WAIT0()  asm volatile("cp.async.wait_group 0;" ::: "memory")

// smem byte offsets (SM_M = 64)
#define OFF_AH   0
#define OFF_AL   33792                 // 64*264*2
#define OFF_B    67584                 // 2 buffers x (Bh 8448 | Bl 8448)
#define BUF_STRIDE 16896
#define OFF_BIAS 101376                // b1 (1024B) | b2 (1024B) | b3 (256B)
#define STEP_SMEM (101376 + 2304)

// ---------------- weight prep: transpose-to-chunks + fp16 split ----------------
__global__ void prep_kernel(const float* __restrict__ W1, const float* __restrict__ W2,
                            const float* __restrict__ W3) {
    int i0 = blockIdx.x*blockDim.x + threadIdx.x, gs = gridDim.x*blockDim.x;
    for (int i = i0; i < 5*9*16*LDB; i += gs) {        // W1: [nd][9][16][264]
        int nd = i/(9*16*LDB), r = i%(9*16*LDB);
        int kc = r/(16*LDB), q = r%(16*LDB), kr = q/LDB, n = q%LDB;
        int k = kc*16 + kr;
        float v = (k < DIN && n < F0) ? W1[((size_t)nd*DIN + k)*F0 + n] : 0.f;
        __half h = __float2half_rn(v);
        g_W1h[i] = h; g_W1l[i] = __float2half_rn(v - __half2float(h));
    }
    for (int i = i0; i < 5*16*16*LDB; i += gs) {       // W2: [nd][16][16][264]
        int nd = i/(16*16*LDB), r = i%(16*16*LDB);
        int kc = r/(16*LDB), q = r%(16*LDB), kr = q/LDB, n = q%LDB;
        int k = kc*16 + kr;
        float v = (n < F0) ? W2[((size_t)nd*F0 + k)*F0 + n] : 0.f;
        __half h = __float2half_rn(v);
        g_W2h[i] = h; g_W2l[i] = __float2half_rn(v - __half2float(h));
    }
    for (int i = i0; i < 5*16*16*LDB3; i += gs) {      // W3: [nd][16][16][72]
        int nd = i/(16*16*LDB3), r = i%(16*16*LDB3);
        int kc = r/(16*LDB3), q = r%(16*LDB3), kr = q/LDB3, n = q%LDB3;
        int k = kc*16 + kr;
        float v = (n < FML) ? W3[((size_t)nd*F0 + k)*FML + n] : 0.f;
        __half h = __float2half_rn(v);
        g_W3h[i] = h; g_W3l[i] = __float2half_rn(v - __half2float(h));
    }
}

// B chunk loader: linear 16B copies, one commit group. n16 = 16B units per part.
__device__ __forceinline__ void loadB(const __half* gh, const __half* gl, int n16,
                                      uint32_t dst, int tid) {
    for (int j = tid; j < n16; j += STHR) {
        cp16(dst + j*16, (const char*)gh + j*16);
        cp16(dst + 8448 + j*16, (const char*)gl + j*16);
    }
    CP_COMMIT();
}

// compute one k16 chunk, N=256 (warp tile 32x64); pass-major mma order (ILP)
__device__ __forceinline__ void chunk256(uint32_t aHaddr, uint32_t aLaddr,
                                         uint32_t bBase, float (&acc)[2][8][4]) {
    uint32_t ah[2][4], al[2][4];
    ldsm4(aHaddr, ah[0]); ldsm4(aHaddr + 16*LDA*2, ah[1]);
    ldsm4(aLaddr, al[0]); ldsm4(aLaddr + 16*LDA*2, al[1]);
#pragma unroll
    for (int g = 0; g < 4; g++) {
        uint32_t bh[4], bl[4];
        ldsm4t(bBase + g*32, bh);
        ldsm4t(bBase + 8448 + g*32, bl);
        // pass 0: ah x bh  (4 independent accs)
#pragma unroll
        for (int mf = 0; mf < 2; mf++)
#pragma unroll
            for (int s = 0; s < 2; s++)
                mma16816(acc[mf][2*g + s], ah[mf], bh[2*s], bh[2*s+1]);
        // pass 1: ah x bl
#pragma unroll
        for (int mf = 0; mf < 2; mf++)
#pragma unroll
            for (int s = 0; s < 2; s++)
                mma16816(acc[mf][2*g + s], ah[mf], bl[2*s], bl[2*s+1]);
        // pass 2: al x bh
#pragma unroll
        for (int mf = 0; mf < 2; mf++)
#pragma unroll
            for (int s = 0; s < 2; s++)
                mma16816(acc[mf][2*g + s], al[mf], bh[2*s], bh[2*s+1]);
    }
}
// compute one k16 chunk, N=64 (warp tile 32x16); pass-major order
__device__ __forceinline__ void chunk64(uint32_t aHaddr, uint32_t aLaddr,
                                        uint32_t bBase, float (&acc)[2][8][4]) {
    uint32_t ah[2][4], al[2][4], bh[4], bl[4];
    ldsm4(aHaddr, ah[0]); ldsm4(aHaddr + 16*LDA*2, ah[1]);
    ldsm4(aLaddr, al[0]); ldsm4(aLaddr + 16*LDA*2, al[1]);
    ldsm4t(bBase, bh);
    ldsm4t(bBase + 8448, bl);
#pragma unroll
    for (int mf = 0; mf < 2; mf++)
#pragma unroll
        for (int s = 0; s < 2; s++)
            mma16816(acc[mf][s], ah[mf], bh[2*s], bh[2*s+1]);
#pragma unroll
    for (int mf = 0; mf < 2; mf++)
#pragma unroll
        for (int s = 0; s < 2; s++)
            mma16816(acc[mf][s], ah[mf], bl[2*s], bl[2*s+1]);
#pragma unroll
    for (int mf = 0; mf < 2; mf++)
#pragma unroll
        for (int s = 0; s < 2; s++)
            mma16816(acc[mf][s], al[mf], bh[2*s], bh[2*s+1]);
}

// epilogue: relu(acc+bias) -> fp16 split -> store into A buffers; zero acc
__device__ __forceinline__ void epiA(float (&acc)[2][8][4], const float* sb,
                                     char* sm, int m0, int n0, int lane) {
#pragma unroll
    for (int mf = 0; mf < 2; mf++)
#pragma unroll
        for (int nf = 0; nf < 8; nf++) {
            int col = n0 + 8*nf + (lane & 3)*2;
            float bx = sb[col], by = sb[col+1];
            int r0 = m0 + 16*mf + (lane >> 2);
            float v00 = fmaxf(acc[mf][nf][0] + bx, 0.f);
            float v01 = fmaxf(acc[mf][nf][1] + by, 0.f);
            float v10 = fmaxf(acc[mf][nf][2] + bx, 0.f);
            float v11 = fmaxf(acc[mf][nf][3] + by, 0.f);
            __half h00 = __float2half_rn(v00), h01 = __float2half_rn(v01);
            __half h10 = __float2half_rn(v10), h11 = __float2half_rn(v11);
            *(__half2*)(sm + OFF_AH + ((size_t)r0*LDA + col)*2)     = __halves2half2(h00, h01);
            *(__half2*)(sm + OFF_AH + ((size_t)(r0+8)*LDA + col)*2) = __halves2half2(h10, h11);
            *(__half2*)(sm + OFF_AL + ((size_t)r0*LDA + col)*2) =
                __halves2half2(__float2half_rn(v00 - __half2float(h00)),
                               __float2half_rn(v01 - __half2float(h01)));
            *(__half2*)(sm + OFF_AL + ((size_t)(r0+8)*LDA + col)*2) =
                __halves2half2(__float2half_rn(v10 - __half2float(h10)),
                               __float2half_rn(v11 - __half2float(h11)));
            acc[mf][nf][0] = acc[mf][nf][1] = acc[mf][nf][2] = acc[mf][nf][3] = 0.f;
        }
}

// ---------------- one recurrent timestep (mma.sync, 2 CTAs/SM) ----------------
__global__ void __launch_bounds__(STHR, 2) step3_kernel(
    const float* __restrict__ x,
    const float* __restrict__ b1, const float* __restrict__ b2,
    const float* __restrict__ b3, int t)
{
    extern __shared__ char sm[];
    const uint32_t smb = smem_to_u32(sm);

    const int tid = threadIdx.x, lane = tid & 31, wid = tid >> 5;
    const int mw = wid >> 2, nwc = wid & 3;      // warp grid 2x4
    const int m0 = mw * 32;
    const int n0 = nwc * 64;                     // N=256 layers
    const int n03 = nwc * 16;                    // N=64 layer
    const int nd = blockIdx.y;
    const int b0 = blockIdx.x * SM_M;
    const int rd = t & 1, wrp = rd ^ 1;
    const int p0 = c_par[nd][0], p1 = c_par[nd][1];

    float* sB1 = (float*)(sm + OFF_BIAS);
    float* sB2 = (float*)(sm + OFF_BIAS + 1024);
    float* sB3 = (float*)(sm + OFF_BIAS + 2048);
    if (tid < 256) { sB1[tid] = b1[nd*F0 + tid]; sB2[tid] = b2[nd*F0 + tid]; }
    if (tid < 64)  sB3[tid] = b3[nd*FML + tid];

    // per-thread ldmatrix base addresses
    const int rowoff = ((lane >> 3) & 1)*8 + (lane & 7);
    const int koffA  = (lane >> 4)*8;
    const uint32_t aH0 = smb + OFF_AH + (((uint32_t)(m0 + rowoff))*LDA + koffA)*2;
    const uint32_t aL0 = smb + OFF_AL + (((uint32_t)(m0 + rowoff))*LDA + koffA)*2;
    const uint32_t bRow = ((lane >> 3) & 1)*8 + (lane & 7);
    const uint32_t bCol = (uint32_t)(lane >> 4)*8;
    const uint32_t bOffL12 = (bRow*LDB + n0 + bCol)*2;
    const uint32_t bOffL3  = (bRow*LDB3 + n03 + bCol)*2;
    const uint32_t bufA[2] = { smb + OFF_B, smb + OFF_B + BUF_STRIDE };

    float acc[2][8][4];
#pragma unroll
    for (int a = 0; a < 2; a++)
#pragma unroll
        for (int b = 0; b < 8; b++)
#pragma unroll
            for (int c = 0; c < 4; c++) acc[a][b][c] = 0.f;

    // prefetch L1 chunk0 into buf0
    loadB(g_W1h + ((size_t)nd*9)*16*LDB, g_W1l + ((size_t)nd*9)*16*LDB, 528, bufA[0], tid);

    // gather L1 input A (fp16 split): cols 0..143 (130..143 zero)
    {
        const float* Sp0 = &g_state2[rd][p0][0][0];
        const float* Sp1 = &g_state2[rd][p1][0][0];
        for (int i = tid; i < SM_M*K1; i += STHR) {
            int r = i / K1, c = i % K1;
            float v = 0.f;
            if (c < 2)        v = x[(size_t)(b0 + r)*(NNODE*T_TOT) + (c ? p1 : p0)*T_TOT + t];
            else if (c < 66)  v = Sp0[(size_t)(b0 + r)*FML + (c - 2)];
            else if (c < 130) v = Sp1[(size_t)(b0 + r)*FML + (c - 66)];
            __half h = __float2half_rn(v);
            *(__half*)(sm + OFF_AH + ((size_t)r*LDA + c)*2) = h;
            *(__half*)(sm + OFF_AL + ((size_t)r*LDA + c)*2) = __float2half_rn(v - __half2float(h));
        }
    }

    // ===== LAYER 1: 9 chunks =====
    for (int kc = 0; kc < 9; kc++) {
        CP_WAIT0();
        __syncthreads();
        if (kc + 1 < 9)
            loadB(g_W1h + ((size_t)nd*9 + kc + 1)*16*LDB,
                  g_W1l + ((size_t)nd*9 + kc + 1)*16*LDB, 528, bufA[(kc+1)&1], tid);
        chunk256(aH0 + kc*32, aL0 + kc*32, bufA[kc&1] + bOffL12, acc);
    }
    // prefetch L2 chunk0 into buf1 (safe: buf1 last read at kc=7, guarded by kc=8 sync)
    loadB(g_W2h + ((size_t)nd*16)*16*LDB, g_W2l + ((size_t)nd*16)*16*LDB, 528, bufA[1], tid);
    __syncthreads();
    epiA(acc, sB1, sm, m0, n0, lane);

    // ===== LAYER 2: 16 chunks =====
    for (int kc = 0; kc < 16; kc++) {
        CP_WAIT0();
        __syncthreads();
        if (kc + 1 < 16)
            loadB(g_W2h + ((size_t)nd*16 + kc + 1)*16*LDB,
                  g_W2l + ((size_t)nd*16 + kc + 1)*16*LDB, 528, bufA[kc&1], tid);
        chunk256(aH0 + kc*32, aL0 + kc*32, bufA[(kc+1)&1] + bOffL12, acc);
    }
    // prefetch L3 chunk0 into buf1
    loadB(g_W3h + ((size_t)nd*16)*16*LDB3, g_W3l + ((size_t)nd*16)*16*LDB3, 144, bufA[1], tid);
    __syncthreads();
    epiA(acc, sB2, sm, m0, n0, lane);

    // ===== LAYER 3: 16 chunks, N=64 =====
    for (int kc = 0; kc < 16; kc++) {
        CP_WAIT0();
        __syncthreads();
        if (kc + 1 < 16)
            loadB(g_W3h + ((size_t)nd*16 + kc + 1)*16*LDB3,
                  g_W3l + ((size_t)nd*16 + kc + 1)*16*LDB3, 144, bufA[kc&1], tid);
        chunk64(aH0 + kc*32, aL0 + kc*32, bufA[(kc+1)&1] + bOffL3, acc);
    }

    // epilogue: state = tanh(acc + b3)
    float* gS = &g_state2[wrp][nd][0][0];
#pragma unroll
    for (int mf = 0; mf < 2; mf++)
#pragma unroll
        for (int nf = 0; nf < 2; nf++) {
            int col = n03 + 8*nf + (lane & 3)*2;
            float bx = sB3[col], by = sB3[col+1];
            int r0 = m0 + 16*mf + (lane >> 2);
            float2 o0, o1;
            o0.x = tanhf(acc[mf][nf][0] + bx);
            o0.y = tanhf(acc[mf][nf][1] + by);
            o1.x = tanhf(acc[mf][nf][2] + bx);
            o1.y = tanhf(acc[mf][nf][3] + by);
            *(float2*)(gS + (size_t)(b0 + r0)*FML + col)     = o0;
            *(float2*)(gS + (size_t)(b0 + r0 + 8)*FML + col) = o1;
        }
}

// ---------------- final head (SIMT) ----------------
__device__ __forceinline__ void ldw256(const float* __restrict__ gW, int K, int kbase,
                                       int tid, float4* pre) {
#pragma unroll
    for (int p = 0; p < 4; p++) {
        int q = p*NTHR + tid, row = q >> 6, c4 = q & 63;
        float4 v = make_float4(0.f, 0.f, 0.f, 0.f);
        if (kbase + row < K) v = *(const float4*)(gW + (size_t)(kbase+row)*256 + c4*4);
        pre[p] = v;
    }
}
__device__ __forceinline__ void stw256(float* sW, int tid, const float4* pre) {
#pragma unroll
    for (int p = 0; p < 4; p++) {
        int q = p*NTHR + tid, row = q >> 6, c4 = q & 63;
        *(float4*)(sW + row*256 + c4*4) = pre[p];
    }
}
__device__ __forceinline__ void gemm256(const float* __restrict__ sA, int lda,
                                        const float* __restrict__ gW, int K,
                                        const float* __restrict__ gb,
                                        float* __restrict__ sOut, int ldo,
                                        float* sW, int tid)
{
    const int tm = tid >> 5, tn = tid & 31;
    const int m0 = tm * 8, n0 = tn * 2;
    ull acc[8][4];
#pragma unroll
    for (int i = 0; i < 8; i++)
#pragma unroll
        for (int j = 0; j < 4; j++) acc[i][j] = 0ull;
    const int nt = (K + KT - 1) / KT;
    float4 pre[4];
    ldw256(gW, K, 0, tid, pre);
    stw256(sW, tid, pre);
    __syncthreads();
    for (int kt = 0; kt < nt; kt++) {
        if (kt + 1 < nt) ldw256(gW, K, (kt+1)*KT, tid, pre);
        const float* Wb = sW + (kt & 1) * (KT*256);
        const float* Arow = sA + m0*lda + kt*KT;
#pragma unroll
        for (int kk = 0; kk < KT; kk++) {
            const ull* bp = (const ull*)(Wb + kk*256 + n0);
            ull w0 = bp[0], w1 = bp[32], w2 = bp[64], w3 = bp[96];
#pragma unroll
            for (int i = 0; i < 8; i++) {
                float a = Arow[i*lda + kk];
                ull aa = pack2(a, a);
                acc[i][0] = fma2(aa, w0, acc[i][0]);
                acc[i][1] = fma2(aa, w1, acc[i][1]);
                acc[i][2] = fma2(aa, w2, acc[i][2]);
                acc[i][3] = fma2(aa, w3, acc[i][3]);
            }
        }
        if (kt + 1 < nt) stw256(sW + ((kt+1) & 1)*(KT*256), tid, pre);
        __syncthreads();
    }
    float2 bb[4];
#pragma unroll
    for (int j = 0; j < 4; j++) bb[j] = *(const float2*)(gb + n0 + 64*j);
#pragma unroll
    for (int i = 0; i < 8; i++)
#pragma unroll
        for (int j = 0; j < 4; j++) {
            float2 v = unpack2(acc[i][j]);
            v.x = fmaxf(v.x + bb[j].x, 0.f);
            v.y = fmaxf(v.y + bb[j].y, 0.f);
            *(float2*)(sOut + (m0+i)*ldo + n0 + 64*j) = v;
        }
}

__global__ __launch_bounds__(NTHR) void final1_kernel(
    const float* __restrict__ x,
    const float* __restrict__ Wo1, const float* __restrict__ bo1)
{
    extern __shared__ float smem[];
    float* sF = smem;
    float* sW = sF + TILE_B*LDF;
    const int tid = threadIdx.x;
    const int b0  = blockIdx.x * TILE_B;
    const float* st = &g_state2[0][0][0][0];

    for (int i = tid; i < TILE_B*320; i += NTHR) {
        int m = i / 320, c = i % 320;
        sF[m*LDF + NNODE + c] = st[((size_t)(c >> 6)*B_TOT + (b0+m))*FML + (c & 63)];
    }
    for (int i = tid; i < TILE_B*NNODE; i += NTHR) {
        int m = i / NNODE, nn = i % NNODE;
        sF[m*LDF + nn] = x[(size_t)(b0+m)*(NNODE*T_TOT) + nn*T_TOT + (T_TOT-1)];
    }
    for (int i = tid; i < TILE_B*(LDF-KFEAT); i += NTHR) {
        int m = i / (LDF-KFEAT), c = KFEAT + i % (LDF-KFEAT);
        sF[m*LDF + c] = 0.f;
    }
    __syncthreads();
    gemm256(sF, LDF, Wo1, KFEAT, bo1, sF, LDF, sW, tid);
    __syncthreads();
    for (int i = tid; i < TILE_B*F0; i += NTHR) {
        int m = i >> 8, c = i & 255;
        g_h[(size_t)(b0+m)*F0 + c] = sF[m*LDF + c];
    }
    float s = 0.f, q = 0.f;
    for (int m = 0; m < TILE_B; m++) {
        float v = sF[m*LDF + tid];
        s += v; q += v*v;
    }
    g_psum[blockIdx.x*F0 + tid] = s;
    g_psq [blockIdx.x*F0 + tid] = q;
}

__global__ void bn_kernel(const float* __restrict__ gamma, const float* __restrict__ beta) {
    int c = threadIdx.x;
    float s = 0.f, q = 0.f;
    for (int b = 0; b < (B_TOT/TILE_B); b++) { s += g_psum[b*F0 + c]; q += g_psq[b*F0 + c]; }
    float mu  = s * (1.f / B_TOT);
    float var = q * (1.f / B_TOT) - mu * mu;
    float sc = gamma[c] * rsqrtf(var + 1e-5f);
    g_scale[c] = sc;
    g_shift[c] = beta[c] - mu * sc;
}

__global__ __launch_bounds__(NTHR) void final2_kernel(
    const float* __restrict__ Wo2, const float* __restrict__ bo2, float* __restrict__ out)
{
    __shared__ float sw2[F0*7], sb2[7], ssc[F0], ssh[F0];
    const int tid = threadIdx.x;
    for (int i = tid; i < F0*7; i += NTHR) sw2[i] = Wo2[i];
    if (tid < 7) sb2[tid] = bo2[tid];
    ssc[tid] = g_scale[tid];
    ssh[tid] = g_shift[tid];
    __syncthreads();
    const int warp = tid >> 5, lane = tid & 31;
    for (int r = 0; r < 16; r++) {
        int b = blockIdx.x*128 + warp*16 + r;
        float a0=0,a1=0,a2=0,a3=0,a4=0,a5=0,a6=0;
        const float* hp = g_h + (size_t)b*F0;
#pragma unroll
        for (int kk = 0; kk < 8; kk++) {
            int k = kk*32 + lane;
            float hv = hp[k]*ssc[k] + ssh[k];
            const float* wrp2 = sw2 + k*7;
            a0 += hv*wrp2[0]; a1 += hv*wrp2[1]; a2 += hv*wrp2[2]; a3 += hv*wrp2[3];
            a4 += hv*wrp2[4]; a5 += hv*wrp2[5]; a6 += hv*wrp2[6];
        }
#pragma unroll
        for (int off = 16; off; off >>= 1) {
            a0 += __shfl_down_sync(0xffffffffu, a0, off);
            a1 += __shfl_down_sync(0xffffffffu, a1, off);
            a2 += __shfl_down_sync(0xffffffffu, a2, off);
            a3 += __shfl_down_sync(0xffffffffu, a3, off);
            a4 += __shfl_down_sync(0xffffffffu, a4, off);
            a5 += __shfl_down_sync(0xffffffffu, a5, off);
            a6 += __shfl_down_sync(0xffffffffu, a6, off);
        }
        if (lane == 0) {
            float l[7] = { a0+sb2[0], a1+sb2[1], a2+sb2[2], a3+sb2[3], a4+sb2[4], a5+sb2[5], a6+sb2[6] };
            float mx = l[0];
#pragma unroll
            for (int j = 1; j < 7; j++) mx = fmaxf(mx, l[j]);
            float e[7], se = 0.f;
#pragma unroll
            for (int j = 0; j < 7; j++) { e[j] = expf(l[j] - mx); se += e[j]; }
            float inv = 1.f / se;
#pragma unroll
            for (int j = 0; j < 7; j++) out[(size_t)b*7 + j] = e[j]*inv;
        }
    }
}

__global__ void zero_state_kernel() {
    size_t n = (size_t)NNODE*B_TOT*FML;
    float* p = &g_state2[0][0][0][0];
    for (size_t i = blockIdx.x*(size_t)blockDim.x + threadIdx.x; i < n;
         i += (size_t)gridDim.x*blockDim.x) p[i] = 0.f;
}

extern "C" void kernel_launch(void* const* d_in, const int* in_sizes, int n_in,
                              void* d_out, int out_size)
{
    (void)in_sizes; (void)n_in; (void)out_size;
    const float* x     = (const float*)d_in[0];
    const float* W1    = (const float*)d_in[1];
    const float* b1    = (const float*)d_in[2];
    const float* W2    = (const float*)d_in[3];
    const float* b2    = (const float*)d_in[4];
    const float* W3    = (const float*)d_in[5];
    const float* b3    = (const float*)d_in[6];
    const float* Wo1   = (const float*)d_in[7];
    const float* bo1   = (const float*)d_in[8];
    const float* gamma = (const float*)d_in[9];
    const float* beta  = (const float*)d_in[10];
    const float* Wo2   = (const float*)d_in[11];
    const float* bo2   = (const float*)d_in[12];
    float* out = (float*)d_out;

    const int F1_SMEM = (TILE_B*LDF + 2*KT*256) * (int)sizeof(float);
    cudaFuncSetAttribute(step3_kernel,  cudaFuncAttributeMaxDynamicSharedMemorySize, STEP_SMEM);
    cudaFuncSetAttribute(final1_kernel, cudaFuncAttributeMaxDynamicSharedMemorySize, F1_SMEM);

    prep_kernel<<<512, 256>>>(W1, W2, W3);
    zero_state_kernel<<<512, 256>>>();

    dim3 sgrid(B_TOT/SM_M, NNODE);   // (128, 5) = 640 CTAs, 2 per SM
    for (int t = 0; t < T_TOT; t++)
        step3_kernel<<<sgrid, STHR, STEP_SMEM>>>(x, b1, b2, b3, t);

    final1_kernel<<<B_TOT/TILE_B, NTHR, F1_SMEM>>>(x, Wo1, bo1);
    bn_kernel<<<1, F0>>>(gamma, beta);
    final2_kernel<<<64, NTHR>>>(Wo2, bo2, out);
}